// round 1
// baseline (speedup 1.0000x reference)
#include <cuda_runtime.h>
#include <math.h>

#define N_ 4096
#define T_ 4
#define F_ 256
#define H_ 8
#define C_ 16
#define P_ 1024
#define D_ 32
#define NT_ (N_*T_)

// ---- scratch (static device globals; no runtime allocation) ----
__device__ float g_feat[N_*F_];        // transformed feature
__device__ float g_recon[NT_*F_];      // reconstruct [N,T,F]
__device__ float g_edgefea[NT_*F_];    // edge_fea    [N,T,F]
__device__ float g_nodeproj[N_*F_];    // node_projd  [N,F]
__device__ float g_edgeproj[NT_*F_];   // edge_projd  [N,T,F]
__device__ float g_rowsum[NT_];
__device__ float g_rowsumsq[NT_];
__device__ float g_rownorm[NT_];

// ============================================================
// K1: g_feat[i,f] = sum_g feature[i,g]*theta_w[f,g] + theta_b[f]
// 16 rows per block, thread = output column f.
// ============================================================
__global__ __launch_bounds__(256) void k1_feature(const float* __restrict__ feature,
                                                  const float* __restrict__ W,
                                                  const float* __restrict__ bias)
{
    __shared__ float As[16][F_];
    const int tid  = threadIdx.x;
    const int base = blockIdx.x * 16;
    #pragma unroll
    for (int r = 0; r < 16; r++)
        As[r][tid] = feature[(size_t)(base + r) * F_ + tid];
    __syncthreads();

    const float* B = W + (size_t)tid * F_;
    float acc[16];
    #pragma unroll
    for (int r = 0; r < 16; r++) acc[r] = 0.f;

    #pragma unroll 4
    for (int k = 0; k < F_; k += 4) {
        float4 bv = *(const float4*)(B + k);
        #pragma unroll
        for (int r = 0; r < 16; r++) {
            float4 av = *(const float4*)(&As[r][k]);
            acc[r] = fmaf(av.x, bv.x, acc[r]);
            acc[r] = fmaf(av.y, bv.y, acc[r]);
            acc[r] = fmaf(av.z, bv.z, acc[r]);
            acc[r] = fmaf(av.w, bv.w, acc[r]);
        }
    }
    float bb = bias[tid];
    #pragma unroll
    for (int r = 0; r < 16; r++)
        g_feat[(size_t)(base + r) * F_ + tid] = acc[r] + bb;
}

// ============================================================
// K2: big GEMM with fused ls generation + row reductions.
//   recon[nt,f] = sum_m relu(linear[nt,m]*mask[nt,m]) * g_feat[m,f]
//   rowsum[nt]  = sum_m ls ;  rowsumsq[nt] = sum_m ls^2
// Block: 64 rows x 256 cols, K-chunks of 16.  Threads 256 (16x16).
// Thread (ty,tx): rows r0..r0+3, cols {tx*4 + j4*64 + e}.
// ============================================================
__global__ __launch_bounds__(256) void k2_big(const float* __restrict__ linear,
                                              const float* __restrict__ mask)
{
    __shared__ float As[64][20];
    __shared__ float Bs[16][260];
    __shared__ float Rs[64][4];
    __shared__ float Rq[64][4];

    const int tid    = threadIdx.x;
    const int ntBase = blockIdx.x * 64;
    const int ty = tid >> 4;          // 0..15
    const int tx = tid & 15;          // 0..15
    const int r0 = ty << 2;           // 4 rows
    const int lrow = tid >> 2;        // A-load row 0..63
    const int lq   = (tid & 3) << 2;  // A-load k offset within chunk
    const int bRow = tid >> 4;        // B-load row 0..15
    const int bCol = (tid & 15) << 4; // B-load col

    float acc[4][16];
    #pragma unroll
    for (int i = 0; i < 4; i++)
        #pragma unroll
        for (int j = 0; j < 16; j++) acc[i][j] = 0.f;

    float psum = 0.f, psq = 0.f;
    const size_t aOff = (size_t)(ntBase + lrow) * N_;

    for (int kb = 0; kb < N_; kb += 16) {
        // --- global loads (pipelined before sync) ---
        float4 l4 = *(const float4*)(linear + aOff + kb + lq);
        float4 m4 = *(const float4*)(mask   + aOff + kb + lq);
        float v0 = fmaxf(l4.x * m4.x, 0.f);
        float v1 = fmaxf(l4.y * m4.y, 0.f);
        float v2 = fmaxf(l4.z * m4.z, 0.f);
        float v3 = fmaxf(l4.w * m4.w, 0.f);
        psum += (v0 + v1) + (v2 + v3);
        psq  = fmaf(v0, v0, psq); psq = fmaf(v1, v1, psq);
        psq  = fmaf(v2, v2, psq); psq = fmaf(v3, v3, psq);

        const float* bp = g_feat + (size_t)(kb + bRow) * F_ + bCol;
        float4 b0 = *(const float4*)(bp + 0);
        float4 b1 = *(const float4*)(bp + 4);
        float4 b2 = *(const float4*)(bp + 8);
        float4 b3 = *(const float4*)(bp + 12);

        __syncthreads();   // previous iteration's smem reads done
        *(float4*)(&As[lrow][lq]) = make_float4(v0, v1, v2, v3);
        *(float4*)(&Bs[bRow][bCol + 0])  = b0;
        *(float4*)(&Bs[bRow][bCol + 4])  = b1;
        *(float4*)(&Bs[bRow][bCol + 8])  = b2;
        *(float4*)(&Bs[bRow][bCol + 12]) = b3;
        __syncthreads();

        #pragma unroll
        for (int kk = 0; kk < 16; kk++) {
            float a0 = As[r0 + 0][kk];
            float a1 = As[r0 + 1][kk];
            float a2 = As[r0 + 2][kk];
            float a3 = As[r0 + 3][kk];
            #pragma unroll
            for (int j4 = 0; j4 < 4; j4++) {
                float4 bv = *(const float4*)(&Bs[kk][(tx << 2) + (j4 << 6)]);
                float bvv[4] = {bv.x, bv.y, bv.z, bv.w};
                #pragma unroll
                for (int e = 0; e < 4; e++) {
                    acc[0][j4 * 4 + e] = fmaf(a0, bvv[e], acc[0][j4 * 4 + e]);
                    acc[1][j4 * 4 + e] = fmaf(a1, bvv[e], acc[1][j4 * 4 + e]);
                    acc[2][j4 * 4 + e] = fmaf(a2, bvv[e], acc[2][j4 * 4 + e]);
                    acc[3][j4 * 4 + e] = fmaf(a3, bvv[e], acc[3][j4 * 4 + e]);
                }
            }
        }
    }

    // --- store recon ---
    #pragma unroll
    for (int i = 0; i < 4; i++) {
        float* rb = g_recon + (size_t)(ntBase + r0 + i) * F_;
        #pragma unroll
        for (int j4 = 0; j4 < 4; j4++) {
            float4 v = make_float4(acc[i][j4 * 4 + 0], acc[i][j4 * 4 + 1],
                                   acc[i][j4 * 4 + 2], acc[i][j4 * 4 + 3]);
            *(float4*)(rb + (tx << 2) + (j4 << 6)) = v;
        }
    }

    // --- row reductions (4 loader-threads per row) ---
    __syncthreads();
    Rs[lrow][tid & 3] = psum;
    Rq[lrow][tid & 3] = psq;
    __syncthreads();
    if ((tid & 3) == 0) {
        float s = (Rs[lrow][0] + Rs[lrow][1]) + (Rs[lrow][2] + Rs[lrow][3]);
        float q = (Rq[lrow][0] + Rq[lrow][1]) + (Rq[lrow][2] + Rq[lrow][3]);
        g_rowsum[ntBase + lrow]   = s;
        g_rowsumsq[ntBase + lrow] = q;
    }
}

// ============================================================
// K3: edge_fea[nt,f] = (recon[nt,f] + feat[n,f]) / (rowsum[nt]+1)
// ============================================================
__global__ __launch_bounds__(256) void k3_edgefea()
{
    int idx = blockIdx.x * 256 + threadIdx.x;
    int f  = idx & (F_ - 1);
    int nt = idx >> 8;
    int n  = nt >> 2;
    g_edgefea[idx] = (g_recon[idx] + g_feat[n * F_ + f]) / (g_rowsum[nt] + 1.f);
}

// ============================================================
// K_inp: inp_proj[i,j,f] = sum_g rp[s,j,f,g]*feat[i,g]   (s = nmm[i])
//        rownorm[i,j] = sqrt(sum_f (inp_proj - recon)^2)
// Grid: (node_tile, j, s) — compute all s, predicated write.
// ============================================================
__global__ __launch_bounds__(256) void k_inp(const float* __restrict__ rp,
                                             const int* __restrict__ nmm)
{
    __shared__ float As[16][F_];
    const int tid  = threadIdx.x;
    const int s    = blockIdx.z;
    const int j    = blockIdx.y;
    const int base = blockIdx.x * 16;

    #pragma unroll
    for (int r = 0; r < 16; r++)
        As[r][tid] = g_feat[(size_t)(base + r) * F_ + tid];
    __syncthreads();

    const float* B = rp + ((size_t)(s * T_ + j)) * F_ * F_ + (size_t)tid * F_;
    float acc[16];
    #pragma unroll
    for (int r = 0; r < 16; r++) acc[r] = 0.f;

    #pragma unroll 4
    for (int k = 0; k < F_; k += 4) {
        float4 bv = *(const float4*)(B + k);
        #pragma unroll
        for (int r = 0; r < 16; r++) {
            float4 av = *(const float4*)(&As[r][k]);
            acc[r] = fmaf(av.x, bv.x, acc[r]);
            acc[r] = fmaf(av.y, bv.y, acc[r]);
            acc[r] = fmaf(av.z, bv.z, acc[r]);
            acc[r] = fmaf(av.w, bv.w, acc[r]);
        }
    }
    __syncthreads();
    #pragma unroll
    for (int r = 0; r < 16; r++) {
        float d = acc[r] - g_recon[((size_t)(base + r) * T_ + j) * F_ + tid];
        As[r][tid] = d * d;
    }
    __syncthreads();

    int w = tid >> 5, lane = tid & 31;
    for (int r = w; r < 16; r += 8) {
        float sv = 0.f;
        #pragma unroll
        for (int c = lane; c < F_; c += 32) sv += As[r][c];
        #pragma unroll
        for (int off = 16; off > 0; off >>= 1)
            sv += __shfl_down_sync(0xffffffffu, sv, off);
        if (lane == 0 && nmm[base + r] == s)
            g_rownorm[(base + r) * T_ + j] = sqrtf(sv);
    }
}

// ============================================================
// K_proj: mode 0: node_projd[i,f]   = sum_g mh_node_proj[s,f,g]*feat[i,g]
//         mode 1: edge_projd[i,j,f] = sum_g ep[s,j,f,g]*edge_fea[i,j,g]
// ============================================================
__global__ __launch_bounds__(256) void k_proj(const float* __restrict__ Ball,
                                              const int* __restrict__ nmm,
                                              int mode)
{
    __shared__ float As[16][F_];
    const float* A  = mode ? g_edgefea  : g_feat;
    float*       out = mode ? g_edgeproj : g_nodeproj;
    const int rowMul = mode ? T_ : 1;
    const int jmulB  = mode ? T_ : 1;

    const int tid  = threadIdx.x;
    const int s    = blockIdx.z;
    const int j    = blockIdx.y;
    const int base = blockIdx.x * 16;

    #pragma unroll
    for (int r = 0; r < 16; r++)
        As[r][tid] = A[((size_t)(base + r) * rowMul + j) * F_ + tid];
    __syncthreads();

    const float* B = Ball + ((size_t)(s * jmulB + j)) * F_ * F_ + (size_t)tid * F_;
    float acc[16];
    #pragma unroll
    for (int r = 0; r < 16; r++) acc[r] = 0.f;

    #pragma unroll 4
    for (int k = 0; k < F_; k += 4) {
        float4 bv = *(const float4*)(B + k);
        #pragma unroll
        for (int r = 0; r < 16; r++) {
            float4 av = *(const float4*)(&As[r][k]);
            acc[r] = fmaf(av.x, bv.x, acc[r]);
            acc[r] = fmaf(av.y, bv.y, acc[r]);
            acc[r] = fmaf(av.z, bv.z, acc[r]);
            acc[r] = fmaf(av.w, bv.w, acc[r]);
        }
    }
    #pragma unroll
    for (int r = 0; r < 16; r++)
        if (nmm[base + r] == s)
            out[((size_t)(base + r) * rowMul + j) * F_ + tid] = acc[r];
}

// ============================================================
// K_attn: per-node attention (softmax over H), relu, sum over T.
// Block = 1 node, 256 threads (tid = h*32 + d).
// ============================================================
__global__ __launch_bounds__(256) void k_attn(float* __restrict__ node_rep)
{
    const int i = blockIdx.x, tid = threadIdx.x;
    const int h = tid >> 5, lane = tid & 31;
    __shared__ float sw[T_][H_];

    float np = g_nodeproj[(size_t)i * F_ + tid];
    const float inv = rsqrtf((float)D_);

    #pragma unroll
    for (int t = 0; t < T_; t++) {
        float v = np * g_edgeproj[((size_t)i * T_ + t) * F_ + tid];
        #pragma unroll
        for (int off = 16; off > 0; off >>= 1)
            v += __shfl_down_sync(0xffffffffu, v, off);
        if (lane == 0) sw[t][h] = v * inv;
    }
    __syncthreads();

    if (tid < T_) {
        int t = tid;
        float mx = sw[t][0];
        #pragma unroll
        for (int hh = 1; hh < H_; hh++) mx = fmaxf(mx, sw[t][hh]);
        float sm = 0.f;
        #pragma unroll
        for (int hh = 0; hh < H_; hh++) {
            float e = expf(sw[t][hh] - mx);
            sw[t][hh] = e;
            sm += e;
        }
        float r = 1.f / sm;
        #pragma unroll
        for (int hh = 0; hh < H_; hh++) sw[t][hh] *= r;
    }
    __syncthreads();

    float rep = 0.f;
    #pragma unroll
    for (int t = 0; t < T_; t++)
        rep += fmaxf(sw[t][h] * g_edgefea[((size_t)i * T_ + t) * F_ + tid], 0.f);
    node_rep[(size_t)i * F_ + tid] = rep;
}

// ============================================================
// K_pred: logits -> sigmoid -> softmax over C.  One warp per p.
// ============================================================
__global__ __launch_bounds__(256) void k_pred(const float* __restrict__ node_rep,
                                              const int* __restrict__ node_idx,
                                              const float* __restrict__ pw,
                                              const float* __restrict__ pb,
                                              float* __restrict__ predict)
{
    const int warp = threadIdx.x >> 5, lane = threadIdx.x & 31;
    const int p = blockIdx.x * 8 + warp;
    const float* a = node_rep + (size_t)node_idx[p] * F_;

    float part[C_];
    #pragma unroll
    for (int c = 0; c < C_; c++) part[c] = 0.f;
    for (int f = lane; f < F_; f += 32) {
        float av = a[f];
        #pragma unroll
        for (int c = 0; c < C_; c++)
            part[c] = fmaf(av, pw[c * F_ + f], part[c]);
    }
    #pragma unroll
    for (int c = 0; c < C_; c++)
        #pragma unroll
        for (int off = 16; off > 0; off >>= 1)
            part[c] += __shfl_down_sync(0xffffffffu, part[c], off);

    if (lane == 0) {
        float sig[C_];
        float mx = -1e30f;
        #pragma unroll
        for (int c = 0; c < C_; c++) {
            float l = part[c] + pb[c];
            float sg = 1.f / (1.f + expf(-l));
            sig[c] = sg;
            mx = fmaxf(mx, sg);
        }
        float sm = 0.f;
        #pragma unroll
        for (int c = 0; c < C_; c++) {
            float e = expf(sig[c] - mx);
            sig[c] = e;
            sm += e;
        }
        float r = 1.f / sm;
        #pragma unroll
        for (int c = 0; c < C_; c++)
            predict[(size_t)p * C_ + c] = sig[c] * r;
    }
}

// ============================================================
// K_reduce: deterministic loss reduction.
//   l1 = sum rowsum ; l2 = sum sqrt(rowsumsq) ; rerr = sum rownorm
//   loss = 0.1*(0.01*rerr + 0.2*l2 + l1)
// ============================================================
__global__ __launch_bounds__(256) void k_reduce(float* __restrict__ lossOut)
{
    __shared__ float s1[256], s2[256], s3[256];
    int tid = threadIdx.x;
    float l1 = 0.f, l2 = 0.f, re = 0.f;
    for (int i = tid; i < NT_; i += 256) {
        l1 += g_rowsum[i];
        l2 += sqrtf(g_rowsumsq[i]);
        re += g_rownorm[i];
    }
    s1[tid] = l1; s2[tid] = l2; s3[tid] = re;
    __syncthreads();
    for (int off = 128; off > 0; off >>= 1) {
        if (tid < off) {
            s1[tid] += s1[tid + off];
            s2[tid] += s2[tid + off];
            s3[tid] += s3[tid + off];
        }
        __syncthreads();
    }
    if (tid == 0)
        lossOut[0] = 0.1f * (0.01f * s3[0] + 0.2f * s2[0] + s1[0]);
}

// ============================================================
extern "C" void kernel_launch(void* const* d_in, const int* in_sizes, int n_in,
                              void* d_out, int out_size)
{
    (void)in_sizes; (void)n_in; (void)out_size;
    const float* feature  = (const float*)d_in[0];
    const float* mask     = (const float*)d_in[1];
    const int*   nmm      = (const int*)  d_in[2];
    const int*   node_idx = (const int*)  d_in[3];
    const float* theta_w  = (const float*)d_in[4];
    const float* theta_b  = (const float*)d_in[5];
    const float* linear   = (const float*)d_in[6];
    const float* rp       = (const float*)d_in[7];
    const float* mhnp     = (const float*)d_in[8];
    const float* mhep     = (const float*)d_in[9];
    const float* pw       = (const float*)d_in[10];
    const float* pb       = (const float*)d_in[11];

    float* out      = (float*)d_out;
    float* predict  = out;                 // [P, C]
    float* loss     = out + P_ * C_;       // scalar
    float* node_rep = out + P_ * C_ + 1;   // [N, F]

    k1_feature<<<N_ / 16, 256>>>(feature, theta_w, theta_b);
    k2_big<<<NT_ / 64, 256>>>(linear, mask);
    k3_edgefea<<<(NT_ * F_) / 256, 256>>>();
    k_inp<<<dim3(N_ / 16, T_, T_), 256>>>(rp, nmm);
    k_proj<<<dim3(N_ / 16, 1, T_), 256>>>(mhnp, nmm, 0);
    k_proj<<<dim3(N_ / 16, T_, T_), 256>>>(mhep, nmm, 1);
    k_attn<<<N_, 256>>>(node_rep);
    k_pred<<<P_ / 8, 256>>>(node_rep, node_idx, pw, pb, predict);
    k_reduce<<<1, 256>>>(loss);
}

// round 2
// speedup vs baseline: 1.6553x; 1.6553x over previous
#include <cuda_runtime.h>
#include <math.h>

#define N_ 4096
#define T_ 4
#define F_ 256
#define H_ 8
#define C_ 16
#define P_ 1024
#define D_ 32
#define NT_ (N_*T_)
#define MAXTILES 67

// ---- scratch (static device globals) ----
__device__ float g_feat[N_*F_];
__device__ float g_recon[NT_*F_];
__device__ float g_edgefea[NT_*F_];
__device__ float g_nodeproj[N_*F_];
__device__ float g_edgeproj[NT_*F_];
__device__ float g_rowsum[NT_];
__device__ float g_rowsumsq[NT_];
__device__ float g_rownorm[NT_];
__device__ float g_BT[37*F_*F_];        // [0]=thetaT, [1..16]=rpT, [17..20]=mhnpT, [21..36]=mhepT
__device__ int   g_perm[N_];
__device__ int   g_tile_s[MAXTILES];
__device__ int   g_tile_start[MAXTILES];
__device__ int   g_tile_cnt[MAXTILES];

// ---- packed f32x2 helpers (FFMA2 path: 2x fp32 pipe) ----
__device__ __forceinline__ unsigned long long pack2(float a) {
    unsigned long long r;
    asm("mov.b64 %0, {%1, %1};" : "=l"(r) : "f"(a));
    return r;
}
__device__ __forceinline__ void ffma2(unsigned long long& d,
                                      unsigned long long a,
                                      unsigned long long b) {
    asm("fma.rn.f32x2 %0, %1, %2, %0;" : "+l"(d) : "l"(a), "l"(b));
}
__device__ __forceinline__ float2 lo_hi(unsigned long long v) {
    float2 f;
    asm("mov.b64 {%0, %1}, %2;" : "=f"(f.x), "=f"(f.y) : "l"(v));
    return f;
}

// ============================================================
// K_transpose: BT[z][g][f] = B[z][f][g] for all 37 weight mats
// ============================================================
__global__ void k_transpose(const float* __restrict__ th,
                            const float* __restrict__ rp,
                            const float* __restrict__ np,
                            const float* __restrict__ ep)
{
    const int z = blockIdx.z;
    const float* src;
    if (z == 0)      src = th;
    else if (z < 17) src = rp + (size_t)(z - 1)  * F_ * F_;
    else if (z < 21) src = np + (size_t)(z - 17) * F_ * F_;
    else             src = ep + (size_t)(z - 21) * F_ * F_;
    float* dst = g_BT + (size_t)z * F_ * F_;

    __shared__ float tile[32][33];
    int x = blockIdx.x * 32 + threadIdx.x;
    int y = blockIdx.y * 32 + threadIdx.y;
    #pragma unroll
    for (int i = 0; i < 32; i += 8)
        tile[threadIdx.y + i][threadIdx.x] = src[(size_t)(y + i) * F_ + x];
    __syncthreads();
    int x2 = blockIdx.y * 32 + threadIdx.x;
    int y2 = blockIdx.x * 32 + threadIdx.y;
    #pragma unroll
    for (int i = 0; i < 32; i += 8)
        dst[(size_t)(y2 + i) * F_ + x2] = tile[threadIdx.x][threadIdx.y + i];
}

// ============================================================
// K_sort: stable counting sort of nodes by nmm + tile descriptors
// ============================================================
__global__ __launch_bounds__(256) void k_sort(const int* __restrict__ nmm)
{
    __shared__ int hist[4][256];
    __shared__ int basep[4][256];
    __shared__ int btot[4];
    __shared__ int boff[4];

    const int tid = threadIdx.x;
    const int r0 = tid * 16;
    int myb[16];
    int c[4] = {0, 0, 0, 0};
    #pragma unroll
    for (int i = 0; i < 16; i++) {
        int b = nmm[r0 + i];
        myb[i] = b;
        c[b]++;
    }
    #pragma unroll
    for (int b = 0; b < 4; b++) hist[b][tid] = c[b];
    __syncthreads();

    const int w = tid >> 5, lane = tid & 31;
    if (w < 4) {
        int b = w;
        int loc[8];
        int sum = 0;
        #pragma unroll
        for (int q = 0; q < 8; q++) {
            loc[q] = sum;
            sum += hist[b][lane * 8 + q];
        }
        int pre = sum;
        #pragma unroll
        for (int off = 1; off < 32; off <<= 1) {
            int v = __shfl_up_sync(0xffffffffu, pre, off);
            if (lane >= off) pre += v;
        }
        int tot = __shfl_sync(0xffffffffu, pre, 31);
        pre -= sum;
        #pragma unroll
        for (int q = 0; q < 8; q++) basep[b][lane * 8 + q] = pre + loc[q];
        if (lane == 31) btot[b] = tot;
    }
    __syncthreads();

    if (tid == 0) {
        int off = 0, t = 0;
        for (int b = 0; b < 4; b++) {
            boff[b] = off;
            int cnt = btot[b];
            for (int k = 0; k < cnt; k += 64) {
                g_tile_s[t] = b;
                g_tile_start[t] = off + k;
                g_tile_cnt[t] = min(64, cnt - k);
                t++;
            }
            off += cnt;
        }
        for (; t < MAXTILES; t++) { g_tile_cnt[t] = 0; g_tile_s[t] = 0; g_tile_start[t] = 0; }
    }
    __syncthreads();

    int pos[4];
    #pragma unroll
    for (int b = 0; b < 4; b++) pos[b] = boff[b] + basep[b][tid];
    #pragma unroll
    for (int i = 0; i < 16; i++) {
        int b = myb[i];
        g_perm[pos[b]++] = r0 + i;
    }
}

// ============================================================
// K1: g_feat = feature @ theta^T + b  (tiled, FFMA2, coalesced BT)
// 64 rows x 256 cols per block, 256 threads.
// ============================================================
__global__ __launch_bounds__(256) void k1b(const float* __restrict__ feature,
                                           const float* __restrict__ bias)
{
    __shared__ float As[64][20];
    __shared__ float Bs[16][260];

    const int tid = threadIdx.x;
    const int base = blockIdx.x * 64;
    const int ty = tid >> 4, tx = tid & 15, r0 = ty << 2;
    const int lrow = tid >> 2, lq = (tid & 3) << 2;
    const int bRow = tid >> 4, bCol = (tid & 15) << 4;

    unsigned long long acc2[4][8];
    #pragma unroll
    for (int i = 0; i < 4; i++)
        #pragma unroll
        for (int k = 0; k < 8; k++) acc2[i][k] = 0ull;

    const float* Arow = feature + (size_t)(base + lrow) * F_;
    const float* BT = g_BT;   // theta transposed

    for (int kb = 0; kb < F_; kb += 16) {
        float4 a4 = *(const float4*)(Arow + kb + lq);
        const float* bp = BT + (size_t)(kb + bRow) * F_ + bCol;
        float4 b0 = *(const float4*)(bp + 0);
        float4 b1 = *(const float4*)(bp + 4);
        float4 b2 = *(const float4*)(bp + 8);
        float4 b3 = *(const float4*)(bp + 12);
        __syncthreads();
        *(float4*)(&As[lrow][lq]) = a4;
        *(float4*)(&Bs[bRow][bCol + 0])  = b0;
        *(float4*)(&Bs[bRow][bCol + 4])  = b1;
        *(float4*)(&Bs[bRow][bCol + 8])  = b2;
        *(float4*)(&Bs[bRow][bCol + 12]) = b3;
        __syncthreads();

        #pragma unroll
        for (int kk = 0; kk < 16; kk++) {
            unsigned long long a2[4];
            #pragma unroll
            for (int i = 0; i < 4; i++) a2[i] = pack2(As[r0 + i][kk]);
            #pragma unroll
            for (int j4 = 0; j4 < 4; j4++) {
                ulonglong2 bv = *(const ulonglong2*)(&Bs[kk][(tx << 2) + (j4 << 6)]);
                #pragma unroll
                for (int i = 0; i < 4; i++) {
                    ffma2(acc2[i][j4 * 2 + 0], a2[i], bv.x);
                    ffma2(acc2[i][j4 * 2 + 1], a2[i], bv.y);
                }
            }
        }
    }

    #pragma unroll
    for (int i = 0; i < 4; i++) {
        float* ob = g_feat + (size_t)(base + r0 + i) * F_;
        #pragma unroll
        for (int j4 = 0; j4 < 4; j4++) {
            int col = (tx << 2) + (j4 << 6);
            float2 p0 = lo_hi(acc2[i][j4 * 2 + 0]);
            float2 p1 = lo_hi(acc2[i][j4 * 2 + 1]);
            float4 v = make_float4(p0.x + bias[col + 0], p0.y + bias[col + 1],
                                   p1.x + bias[col + 2], p1.y + bias[col + 3]);
            *(float4*)(ob + col) = v;
        }
    }
}

// ============================================================
// K2: big GEMM (fused ls gen + rowsum/sq + recon + edge_fea)
// ============================================================
__global__ __launch_bounds__(256) void k2_big(const float* __restrict__ linear,
                                              const float* __restrict__ mask)
{
    __shared__ float As[64][20];
    __shared__ float Bs[16][260];
    __shared__ float Rs[64][4];
    __shared__ float Rq[64][4];
    __shared__ float rsum[64];

    const int tid = threadIdx.x;
    const int ntBase = blockIdx.x * 64;
    const int ty = tid >> 4, tx = tid & 15, r0 = ty << 2;
    const int lrow = tid >> 2, lq = (tid & 3) << 2;
    const int bRow = tid >> 4, bCol = (tid & 15) << 4;

    unsigned long long acc2[4][8];
    #pragma unroll
    for (int i = 0; i < 4; i++)
        #pragma unroll
        for (int k = 0; k < 8; k++) acc2[i][k] = 0ull;

    float psum = 0.f, psq = 0.f;
    const size_t aOff = (size_t)(ntBase + lrow) * N_;

    for (int kb = 0; kb < N_; kb += 16) {
        float4 l4 = *(const float4*)(linear + aOff + kb + lq);
        float4 m4 = *(const float4*)(mask   + aOff + kb + lq);
        float v0 = fmaxf(l4.x * m4.x, 0.f);
        float v1 = fmaxf(l4.y * m4.y, 0.f);
        float v2 = fmaxf(l4.z * m4.z, 0.f);
        float v3 = fmaxf(l4.w * m4.w, 0.f);
        psum += (v0 + v1) + (v2 + v3);
        psq = fmaf(v0, v0, psq); psq = fmaf(v1, v1, psq);
        psq = fmaf(v2, v2, psq); psq = fmaf(v3, v3, psq);

        const float* bp = g_feat + (size_t)(kb + bRow) * F_ + bCol;
        float4 b0 = *(const float4*)(bp + 0);
        float4 b1 = *(const float4*)(bp + 4);
        float4 b2 = *(const float4*)(bp + 8);
        float4 b3 = *(const float4*)(bp + 12);

        __syncthreads();
        *(float4*)(&As[lrow][lq]) = make_float4(v0, v1, v2, v3);
        *(float4*)(&Bs[bRow][bCol + 0])  = b0;
        *(float4*)(&Bs[bRow][bCol + 4])  = b1;
        *(float4*)(&Bs[bRow][bCol + 8])  = b2;
        *(float4*)(&Bs[bRow][bCol + 12]) = b3;
        __syncthreads();

        #pragma unroll
        for (int kk = 0; kk < 16; kk++) {
            unsigned long long a2[4];
            #pragma unroll
            for (int i = 0; i < 4; i++) a2[i] = pack2(As[r0 + i][kk]);
            #pragma unroll
            for (int j4 = 0; j4 < 4; j4++) {
                ulonglong2 bv = *(const ulonglong2*)(&Bs[kk][(tx << 2) + (j4 << 6)]);
                #pragma unroll
                for (int i = 0; i < 4; i++) {
                    ffma2(acc2[i][j4 * 2 + 0], a2[i], bv.x);
                    ffma2(acc2[i][j4 * 2 + 1], a2[i], bv.y);
                }
            }
        }
    }

    // recon store
    #pragma unroll
    for (int i = 0; i < 4; i++) {
        float* rb = g_recon + (size_t)(ntBase + r0 + i) * F_;
        #pragma unroll
        for (int j4 = 0; j4 < 4; j4++) {
            ulonglong2 v;
            v.x = acc2[i][j4 * 2 + 0];
            v.y = acc2[i][j4 * 2 + 1];
            *(ulonglong2*)(rb + (tx << 2) + (j4 << 6)) = v;
        }
    }

    // row reductions
    __syncthreads();
    Rs[lrow][tid & 3] = psum;
    Rq[lrow][tid & 3] = psq;
    __syncthreads();
    if ((tid & 3) == 0) {
        float s = (Rs[lrow][0] + Rs[lrow][1]) + (Rs[lrow][2] + Rs[lrow][3]);
        float q = (Rq[lrow][0] + Rq[lrow][1]) + (Rq[lrow][2] + Rq[lrow][3]);
        g_rowsum[ntBase + lrow]   = s;
        g_rowsumsq[ntBase + lrow] = q;
        rsum[lrow] = s;
    }
    __syncthreads();

    // fused edge_fea
    #pragma unroll
    for (int i = 0; i < 4; i++) {
        int nt = ntBase + r0 + i;
        float inv = 1.f / (rsum[r0 + i] + 1.f);
        const float* fb = g_feat + (size_t)(nt >> 2) * F_;
        float* eb = g_edgefea + (size_t)nt * F_;
        #pragma unroll
        for (int j4 = 0; j4 < 4; j4++) {
            int col = (tx << 2) + (j4 << 6);
            float2 p0 = lo_hi(acc2[i][j4 * 2 + 0]);
            float2 p1 = lo_hi(acc2[i][j4 * 2 + 1]);
            float4 fv = *(const float4*)(fb + col);
            float4 v = make_float4((p0.x + fv.x) * inv, (p0.y + fv.y) * inv,
                                   (p1.x + fv.z) * inv, (p1.y + fv.w) * inv);
            *(float4*)(eb + col) = v;
        }
    }
}

// ============================================================
// K_bgemm<MODE>: bucketed projection GEMMs.
//  MODE 0 (inp):  A=feat[node],        B=rpT[s,j],  out: rownorm (diff vs recon)
//  MODE 1 (node): A=feat[node],        B=mhnpT[s],  out: nodeproj[node]
//  MODE 2 (edge): A=edgefea[node,j],   B=mhepT[s,j],out: edgeproj[node,j]
// ============================================================
template<int MODE>
__global__ __launch_bounds__(256) void k_bgemm()
{
    const int t = blockIdx.x;
    const int cnt = g_tile_cnt[t];
    if (cnt == 0) return;
    const int s = g_tile_s[t];
    const int j = blockIdx.y;
    const int start = g_tile_start[t];

    __shared__ int idx[64];
    __shared__ float As[64][20];
    __shared__ float Bs[16][260];

    const int tid = threadIdx.x;
    if (tid < 64) idx[tid] = g_perm[start + min(tid, cnt - 1)];
    __syncthreads();

    const float* BT;
    if (MODE == 0)      BT = g_BT + (size_t)(1 + s * T_ + j) * F_ * F_;
    else if (MODE == 1) BT = g_BT + (size_t)(17 + s) * F_ * F_;
    else                BT = g_BT + (size_t)(21 + s * T_ + j) * F_ * F_;

    const int ty = tid >> 4, tx = tid & 15, r0 = ty << 2;
    const int lrow = tid >> 2, lq = (tid & 3) << 2;
    const int bRow = tid >> 4, bCol = (tid & 15) << 4;

    const int node_l = idx[lrow];
    const float* Arow;
    if (MODE == 2) Arow = g_edgefea + ((size_t)node_l * T_ + j) * F_;
    else           Arow = g_feat + (size_t)node_l * F_;

    unsigned long long acc2[4][8];
    #pragma unroll
    for (int i = 0; i < 4; i++)
        #pragma unroll
        for (int k = 0; k < 8; k++) acc2[i][k] = 0ull;

    for (int kb = 0; kb < F_; kb += 16) {
        float4 a4 = *(const float4*)(Arow + kb + lq);
        const float* bp = BT + (size_t)(kb + bRow) * F_ + bCol;
        float4 b0 = *(const float4*)(bp + 0);
        float4 b1 = *(const float4*)(bp + 4);
        float4 b2 = *(const float4*)(bp + 8);
        float4 b3 = *(const float4*)(bp + 12);
        __syncthreads();
        *(float4*)(&As[lrow][lq]) = a4;
        *(float4*)(&Bs[bRow][bCol + 0])  = b0;
        *(float4*)(&Bs[bRow][bCol + 4])  = b1;
        *(float4*)(&Bs[bRow][bCol + 8])  = b2;
        *(float4*)(&Bs[bRow][bCol + 12]) = b3;
        __syncthreads();

        #pragma unroll
        for (int kk = 0; kk < 16; kk++) {
            unsigned long long a2[4];
            #pragma unroll
            for (int i = 0; i < 4; i++) a2[i] = pack2(As[r0 + i][kk]);
            #pragma unroll
            for (int j4 = 0; j4 < 4; j4++) {
                ulonglong2 bv = *(const ulonglong2*)(&Bs[kk][(tx << 2) + (j4 << 6)]);
                #pragma unroll
                for (int i = 0; i < 4; i++) {
                    ffma2(acc2[i][j4 * 2 + 0], a2[i], bv.x);
                    ffma2(acc2[i][j4 * 2 + 1], a2[i], bv.y);
                }
            }
        }
    }

    if (MODE == 0) {
        #pragma unroll
        for (int i = 0; i < 4; i++) {
            int node = idx[r0 + i];
            const float* rr = g_recon + ((size_t)node * T_ + j) * F_;
            float part = 0.f;
            #pragma unroll
            for (int j4 = 0; j4 < 4; j4++) {
                int col = (tx << 2) + (j4 << 6);
                float2 p0 = lo_hi(acc2[i][j4 * 2 + 0]);
                float2 p1 = lo_hi(acc2[i][j4 * 2 + 1]);
                float4 rv = *(const float4*)(rr + col);
                float d0 = p0.x - rv.x, d1 = p0.y - rv.y;
                float d2 = p1.x - rv.z, d3 = p1.y - rv.w;
                part = fmaf(d0, d0, part); part = fmaf(d1, d1, part);
                part = fmaf(d2, d2, part); part = fmaf(d3, d3, part);
            }
            #pragma unroll
            for (int m = 8; m > 0; m >>= 1)
                part += __shfl_xor_sync(0xffffffffu, part, m);
            if (tx == 0 && (r0 + i) < cnt)
                g_rownorm[node * T_ + j] = sqrtf(part);
        }
    } else {
        #pragma unroll
        for (int i = 0; i < 4; i++) {
            if ((r0 + i) >= cnt) continue;
            int node = idx[r0 + i];
            float* ob;
            if (MODE == 1) ob = g_nodeproj + (size_t)node * F_;
            else           ob = g_edgeproj + ((size_t)node * T_ + j) * F_;
            #pragma unroll
            for (int j4 = 0; j4 < 4; j4++) {
                ulonglong2 v;
                v.x = acc2[i][j4 * 2 + 0];
                v.y = acc2[i][j4 * 2 + 1];
                *(ulonglong2*)(ob + (tx << 2) + (j4 << 6)) = v;
            }
        }
    }
}

// ============================================================
// K_attn: per-node attention (softmax over H), relu, sum over T
// ============================================================
__global__ __launch_bounds__(256) void k_attn(float* __restrict__ node_rep)
{
    const int i = blockIdx.x, tid = threadIdx.x;
    const int h = tid >> 5, lane = tid & 31;
    __shared__ float sw[T_][H_];

    float np = g_nodeproj[(size_t)i * F_ + tid];
    const float inv = rsqrtf((float)D_);

    #pragma unroll
    for (int t = 0; t < T_; t++) {
        float v = np * g_edgeproj[((size_t)i * T_ + t) * F_ + tid];
        #pragma unroll
        for (int off = 16; off > 0; off >>= 1)
            v += __shfl_down_sync(0xffffffffu, v, off);
        if (lane == 0) sw[t][h] = v * inv;
    }
    __syncthreads();

    if (tid < T_) {
        int t = tid;
        float mx = sw[t][0];
        #pragma unroll
        for (int hh = 1; hh < H_; hh++) mx = fmaxf(mx, sw[t][hh]);
        float sm = 0.f;
        #pragma unroll
        for (int hh = 0; hh < H_; hh++) {
            float e = expf(sw[t][hh] - mx);
            sw[t][hh] = e;
            sm += e;
        }
        float r = 1.f / sm;
        #pragma unroll
        for (int hh = 0; hh < H_; hh++) sw[t][hh] *= r;
    }
    __syncthreads();

    float rep = 0.f;
    #pragma unroll
    for (int t = 0; t < T_; t++)
        rep += fmaxf(sw[t][h] * g_edgefea[((size_t)i * T_ + t) * F_ + tid], 0.f);
    node_rep[(size_t)i * F_ + tid] = rep;
}

// ============================================================
// K_pred
// ============================================================
__global__ __launch_bounds__(256) void k_pred(const float* __restrict__ node_rep,
                                              const int* __restrict__ node_idx,
                                              const float* __restrict__ pw,
                                              const float* __restrict__ pb,
                                              float* __restrict__ predict)
{
    const int warp = threadIdx.x >> 5, lane = threadIdx.x & 31;
    const int p = blockIdx.x * 8 + warp;
    const float* a = node_rep + (size_t)node_idx[p] * F_;

    float part[C_];
    #pragma unroll
    for (int c = 0; c < C_; c++) part[c] = 0.f;
    for (int f = lane; f < F_; f += 32) {
        float av = a[f];
        #pragma unroll
        for (int c = 0; c < C_; c++)
            part[c] = fmaf(av, pw[c * F_ + f], part[c]);
    }
    #pragma unroll
    for (int c = 0; c < C_; c++)
        #pragma unroll
        for (int off = 16; off > 0; off >>= 1)
            part[c] += __shfl_down_sync(0xffffffffu, part[c], off);

    if (lane == 0) {
        float sig[C_];
        float mx = -1e30f;
        #pragma unroll
        for (int c = 0; c < C_; c++) {
            float l = part[c] + pb[c];
            float sg = 1.f / (1.f + expf(-l));
            sig[c] = sg;
            mx = fmaxf(mx, sg);
        }
        float sm = 0.f;
        #pragma unroll
        for (int c = 0; c < C_; c++) {
            float e = expf(sig[c] - mx);
            sig[c] = e;
            sm += e;
        }
        float r = 1.f / sm;
        #pragma unroll
        for (int c = 0; c < C_; c++)
            predict[(size_t)p * C_ + c] = sig[c] * r;
    }
}

// ============================================================
// K_reduce: loss
// ============================================================
__global__ __launch_bounds__(256) void k_reduce(float* __restrict__ lossOut)
{
    __shared__ float s1[256], s2[256], s3[256];
    int tid = threadIdx.x;
    float l1 = 0.f, l2 = 0.f, re = 0.f;
    for (int i = tid; i < NT_; i += 256) {
        l1 += g_rowsum[i];
        l2 += sqrtf(g_rowsumsq[i]);
        re += g_rownorm[i];
    }
    s1[tid] = l1; s2[tid] = l2; s3[tid] = re;
    __syncthreads();
    for (int off = 128; off > 0; off >>= 1) {
        if (tid < off) {
            s1[tid] += s1[tid + off];
            s2[tid] += s2[tid + off];
            s3[tid] += s3[tid + off];
        }
        __syncthreads();
    }
    if (tid == 0)
        lossOut[0] = 0.1f * (0.01f * s3[0] + 0.2f * s2[0] + s1[0]);
}

// ============================================================
extern "C" void kernel_launch(void* const* d_in, const int* in_sizes, int n_in,
                              void* d_out, int out_size)
{
    (void)in_sizes; (void)n_in; (void)out_size;
    const float* feature  = (const float*)d_in[0];
    const float* mask     = (const float*)d_in[1];
    const int*   nmm      = (const int*)  d_in[2];
    const int*   node_idx = (const int*)  d_in[3];
    const float* theta_w  = (const float*)d_in[4];
    const float* theta_b  = (const float*)d_in[5];
    const float* linear   = (const float*)d_in[6];
    const float* rp       = (const float*)d_in[7];
    const float* mhnp     = (const float*)d_in[8];
    const float* mhep     = (const float*)d_in[9];
    const float* pw       = (const float*)d_in[10];
    const float* pb       = (const float*)d_in[11];

    float* out      = (float*)d_out;
    float* predict  = out;
    float* loss     = out + P_ * C_;
    float* node_rep = out + P_ * C_ + 1;

    k_transpose<<<dim3(8, 8, 37), dim3(32, 8)>>>(theta_w, rp, mhnp, mhep);
    k_sort<<<1, 256>>>(nmm);
    k1b<<<N_ / 64, 256>>>(feature, theta_b);
    k2_big<<<NT_ / 64, 256>>>(linear, mask);
    k_bgemm<0><<<dim3(MAXTILES, T_), 256>>>();
    k_bgemm<1><<<dim3(MAXTILES, 1), 256>>>();
    k_bgemm<2><<<dim3(MAXTILES, T_), 256>>>();
    k_attn<<<N_, 256>>>(node_rep);
    k_pred<<<P_ / 8, 256>>>(node_rep, node_idx, pw, pb, predict);
    k_reduce<<<1, 256>>>(loss);
}

// round 4
// speedup vs baseline: 3.4611x; 2.0910x over previous
#include <cuda_runtime.h>
#include <cuda_bf16.h>
#include <math.h>
#include <stdint.h>

#define N_ 4096
#define T_ 4
#define F_ 256
#define H_ 8
#define C_ 16
#define P_ 1024
#define D_ 32
#define NT_ (N_*T_)
#define MAXTILES 67

#define BM 128
#define BK 32
#define NCHUNK (N_/BK)
#define APAD 40
#define BPAD 40

// dynamic smem offsets (bytes) for k2_mma
#define OFF_A(s,hl)  (((s)*2+(hl)) * (BM*APAD*2))
#define OFF_B(s,hl)  (40960 + ((s)*2+(hl)) * (256*BPAD*2))
#define OFF_RS       122880
#define OFF_RQ       (122880+2048)
#define OFF_RINV     (122880+4096)
#define SMEM_K2      (122880+4096+512+128)

// ---- scratch (static device globals) ----
__device__ float g_feat[N_*F_];
__device__ float g_recon[NT_*F_];
__device__ float g_edgefea[NT_*F_];
__device__ float g_nodeproj[N_*F_];
__device__ float g_edgeproj[NT_*F_];
__device__ float g_rowsum[NT_];
__device__ float g_rowsumsq[NT_];
__device__ float g_rownorm[NT_];
__device__ float g_BT[37*F_*F_];
__device__ int   g_perm[N_];
__device__ int   g_tile_s[MAXTILES];
__device__ int   g_tile_start[MAXTILES];
__device__ int   g_tile_cnt[MAXTILES];
__device__ __align__(16) __nv_bfloat16 g_fT_hi[F_*N_];
__device__ __align__(16) __nv_bfloat16 g_fT_lo[F_*N_];

// ---- packed f32x2 helpers ----
__device__ __forceinline__ unsigned long long pack2(float a) {
    unsigned long long r;
    asm("mov.b64 %0, {%1, %1};" : "=l"(r) : "f"(a));
    return r;
}
__device__ __forceinline__ void ffma2(unsigned long long& d,
                                      unsigned long long a,
                                      unsigned long long b) {
    asm("fma.rn.f32x2 %0, %1, %2, %0;" : "+l"(d) : "l"(a), "l"(b));
}
__device__ __forceinline__ float2 lo_hi(unsigned long long v) {
    float2 f;
    asm("mov.b64 {%0, %1}, %2;" : "=f"(f.x), "=f"(f.y) : "l"(v));
    return f;
}

// ---- mma.sync / ldmatrix / cp.async helpers (sm_80+, legal on compute_103) ----
__device__ __forceinline__ uint32_t smem_u32(const void* p) {
    uint32_t a;
    asm("{ .reg .u64 t; cvta.to.shared.u64 t, %1; cvt.u32.u64 %0, t; }"
        : "=r"(a) : "l"(p));
    return a;
}
__device__ __forceinline__ void ldm_x4(uint32_t* r, uint32_t addr) {
    asm volatile("ldmatrix.sync.aligned.m8n8.x4.shared.b16 {%0,%1,%2,%3}, [%4];"
                 : "=r"(r[0]), "=r"(r[1]), "=r"(r[2]), "=r"(r[3]) : "r"(addr));
}
__device__ __forceinline__ void mma_bf16(float* d, const uint32_t* a,
                                         uint32_t b0, uint32_t b1) {
    asm volatile("mma.sync.aligned.m16n8k16.row.col.f32.bf16.bf16.f32 "
                 "{%0,%1,%2,%3}, {%4,%5,%6,%7}, {%8,%9}, {%0,%1,%2,%3};"
                 : "+f"(d[0]), "+f"(d[1]), "+f"(d[2]), "+f"(d[3])
                 : "r"(a[0]), "r"(a[1]), "r"(a[2]), "r"(a[3]), "r"(b0), "r"(b1));
}
__device__ __forceinline__ void cpa16(uint32_t dst, const void* src) {
    asm volatile("cp.async.ca.shared.global [%0], [%1], 16;" :: "r"(dst), "l"(src));
}
#define CP_COMMIT() asm volatile("cp.async.commit_group;" ::: "memory")
#define CP_WAIT0()  asm volatile("cp.async.wait_group 0;"  ::: "memory")

// ls generation + bf16 hi/lo pack (8 values)
__device__ __forceinline__ void pack_ls(const float* lp, const float* mp,
                                        float& psum, float& psq,
                                        uint32_t* Ah, uint32_t* Al)
{
    float4 L0 = *(const float4*)lp;
    float4 L1 = *(const float4*)(lp + 4);
    float4 M0 = *(const float4*)mp;
    float4 M1 = *(const float4*)(mp + 4);
    float v[8];
    v[0] = fmaxf(L0.x * M0.x, 0.f); v[1] = fmaxf(L0.y * M0.y, 0.f);
    v[2] = fmaxf(L0.z * M0.z, 0.f); v[3] = fmaxf(L0.w * M0.w, 0.f);
    v[4] = fmaxf(L1.x * M1.x, 0.f); v[5] = fmaxf(L1.y * M1.y, 0.f);
    v[6] = fmaxf(L1.z * M1.z, 0.f); v[7] = fmaxf(L1.w * M1.w, 0.f);
    #pragma unroll
    for (int i = 0; i < 8; i++) { psum += v[i]; psq = fmaf(v[i], v[i], psq); }
    #pragma unroll
    for (int p = 0; p < 4; p++) {
        __nv_bfloat162 hp = __floats2bfloat162_rn(v[2*p], v[2*p+1]);
        float r0 = v[2*p]   - __bfloat162float(hp.x);
        float r1 = v[2*p+1] - __bfloat162float(hp.y);
        __nv_bfloat162 lw = __floats2bfloat162_rn(r0, r1);
        Ah[p] = *(uint32_t*)&hp;
        Al[p] = *(uint32_t*)&lw;
    }
}

// ============================================================
// K2-MMA: recon = ls @ feat via mma.sync bf16 hi/lo (3 MMAs),
// fused ls gen + rowsum/rowsumsq + recon + edge_fea.
// 512 threads = 16 warps (4m x 4n); BM=128, BN=256, BK=32.
// ============================================================
__global__ __launch_bounds__(512, 1) void k2_mma(const float* __restrict__ linear,
                                                 const float* __restrict__ mask)
{
    extern __shared__ char sm[];
    const uint32_t sb = smem_u32(sm);
    const int tid = threadIdx.x;
    const int wid = tid >> 5, lane = tid & 31;
    const int warp_m = wid & 3, warp_n = wid >> 2;
    const int ntBase = blockIdx.x * BM;

    // A producer mapping
    const int arow = tid >> 2;
    const int akof = (tid & 3) * 8;
    const float* lptr = linear + (size_t)(ntBase + arow) * N_ + akof;
    const float* mptr = mask   + (size_t)(ntBase + arow) * N_ + akof;
    const uint32_t aSt = (uint32_t)(arow * APAD + akof) * 2;

    // B producer mapping (cp.async)
    const int bhl = tid >> 8;
    const int bn  = tid & 255;
    const char* bsrc = (const char*)((bhl ? g_fT_lo : g_fT_hi) + (size_t)bn * N_);
    const uint32_t bSt = (uint32_t)(bn * BPAD) * 2;

    float psum = 0.f, psq = 0.f;
    uint32_t Ah[4], Al[4];

    // ldmatrix lane addressing
    const int aRowL = warp_m * 32 + (lane & 7) + ((lane >> 3) & 1) * 8;
    const int aColL = (lane >> 4) * 8;
    const int bRowL = warp_n * 64 + (lane & 7) + ((lane >> 4) & 1) * 8;
    const int bColL = ((lane >> 3) & 1) * 8;

    // ---- prologue: chunk 0 ----
    pack_ls(lptr, mptr, psum, psq, Ah, Al);
    {
        uint32_t d = sb + OFF_B(0, bhl) + bSt;
        #pragma unroll
        for (int q = 0; q < 4; q++) cpa16(d + q * 16, bsrc + q * 16);
    }
    CP_COMMIT(); CP_WAIT0();
    __syncthreads();
    *(uint4*)(sm + OFF_A(0,0) + aSt) = make_uint4(Ah[0], Ah[1], Ah[2], Ah[3]);
    *(uint4*)(sm + OFF_A(0,1) + aSt) = make_uint4(Al[0], Al[1], Al[2], Al[3]);
    __syncthreads();

    float acc[2][8][4];
    #pragma unroll
    for (int i = 0; i < 2; i++)
        #pragma unroll
        for (int j = 0; j < 8; j++)
            #pragma unroll
            for (int q = 0; q < 4; q++) acc[i][j][q] = 0.f;

    for (int c = 0; c < NCHUNK; c++) {
        const int s = c & 1;
        if (c + 1 < NCHUNK) {
            uint32_t d = sb + OFF_B(s ^ 1, bhl) + bSt;
            const char* src = bsrc + (size_t)(c + 1) * BK * 2;
            #pragma unroll
            for (int q = 0; q < 4; q++) cpa16(d + q * 16, src + q * 16);
            CP_COMMIT();
            pack_ls(lptr + (c + 1) * BK, mptr + (c + 1) * BK, psum, psq, Ah, Al);
        }

        const uint32_t aHi = sb + OFF_A(s,0), aLo = sb + OFF_A(s,1);
        const uint32_t bHi = sb + OFF_B(s,0), bLo = sb + OFF_B(s,1);

        #pragma unroll
        for (int ks = 0; ks < BK; ks += 16) {
            uint32_t ah[2][4], alr[2][4], bb[4][4];
            ldm_x4(ah[0], aHi + (uint32_t)((aRowL)      * APAD + ks + aColL) * 2);
            ldm_x4(ah[1], aHi + (uint32_t)((aRowL + 16) * APAD + ks + aColL) * 2);
            #pragma unroll
            for (int g = 0; g < 4; g++)
                ldm_x4(bb[g], bHi + (uint32_t)((bRowL + g * 16) * BPAD + ks + bColL) * 2);
            #pragma unroll
            for (int mf = 0; mf < 2; mf++)
                #pragma unroll
                for (int nf = 0; nf < 8; nf++)
                    mma_bf16(acc[mf][nf], ah[mf],
                             bb[nf >> 1][(nf & 1) * 2], bb[nf >> 1][(nf & 1) * 2 + 1]);
            ldm_x4(alr[0], aLo + (uint32_t)((aRowL)      * APAD + ks + aColL) * 2);
            ldm_x4(alr[1], aLo + (uint32_t)((aRowL + 16) * APAD + ks + aColL) * 2);
            #pragma unroll
            for (int mf = 0; mf < 2; mf++)
                #pragma unroll
                for (int nf = 0; nf < 8; nf++)
                    mma_bf16(acc[mf][nf], alr[mf],
                             bb[nf >> 1][(nf & 1) * 2], bb[nf >> 1][(nf & 1) * 2 + 1]);
            #pragma unroll
            for (int g = 0; g < 4; g++)
                ldm_x4(bb[g], bLo + (uint32_t)((bRowL + g * 16) * BPAD + ks + bColL) * 2);
            #pragma unroll
            for (int mf = 0; mf < 2; mf++)
                #pragma unroll
                for (int nf = 0; nf < 8; nf++)
                    mma_bf16(acc[mf][nf], ah[mf],
                             bb[nf >> 1][(nf & 1) * 2], bb[nf >> 1][(nf & 1) * 2 + 1]);
        }

        if (c + 1 < NCHUNK) {
            CP_WAIT0();
            __syncthreads();
            *(uint4*)(sm + OFF_A(s^1,0) + aSt) = make_uint4(Ah[0], Ah[1], Ah[2], Ah[3]);
            *(uint4*)(sm + OFF_A(s^1,1) + aSt) = make_uint4(Al[0], Al[1], Al[2], Al[3]);
            __syncthreads();
        }
    }

    // ---- row reductions ----
    ((float*)(sm + OFF_RS))[arow * 4 + (tid & 3)] = psum;
    ((float*)(sm + OFF_RQ))[arow * 4 + (tid & 3)] = psq;
    __syncthreads();
    if (tid < BM) {
        const float* rs = (const float*)(sm + OFF_RS) + tid * 4;
        const float* rq = (const float*)(sm + OFF_RQ) + tid * 4;
        float ss = (rs[0] + rs[1]) + (rs[2] + rs[3]);
        float sq = (rq[0] + rq[1]) + (rq[2] + rq[3]);
        g_rowsum[ntBase + tid]   = ss;
        g_rowsumsq[ntBase + tid] = sq;
        ((float*)(sm + OFF_RINV))[tid] = 1.f / (ss + 1.f);
    }
    __syncthreads();
    const float* rinv = (const float*)(sm + OFF_RINV);

    // ---- epilogue: recon + edge_fea ----
    #pragma unroll
    for (int mf = 0; mf < 2; mf++) {
        #pragma unroll
        for (int half = 0; half < 2; half++) {
            int row = warp_m * 32 + mf * 16 + half * 8 + (lane >> 2);
            int nt = ntBase + row;
            float inv = rinv[row];
            const float* fb = g_feat + (size_t)(nt >> 2) * F_;
            float* rb = g_recon   + (size_t)nt * F_;
            float* eb = g_edgefea + (size_t)nt * F_;
            #pragma unroll
            for (int nf = 0; nf < 8; nf++) {
                int col = warp_n * 64 + nf * 8 + (lane & 3) * 2;
                float d0 = acc[mf][nf][half * 2];
                float d1 = acc[mf][nf][half * 2 + 1];
                *(float2*)(rb + col) = make_float2(d0, d1);
                float2 fv = *(const float2*)(fb + col);
                *(float2*)(eb + col) = make_float2((d0 + fv.x) * inv, (d1 + fv.y) * inv);
            }
        }
    }
}

// ============================================================
// K_featT: featT hi/lo bf16 [F_][N_] from g_feat
// ============================================================
__global__ void k_featT()
{
    __shared__ float tile[32][33];
    int x = blockIdx.x * 32 + threadIdx.x;
    int y = blockIdx.y * 32 + threadIdx.y;
    #pragma unroll
    for (int i = 0; i < 32; i += 8)
        tile[threadIdx.y + i][threadIdx.x] = g_feat[(size_t)(y + i) * F_ + x];
    __syncthreads();
    int f2 = blockIdx.x * 32 + threadIdx.y;
    int n2 = blockIdx.y * 32 + threadIdx.x;
    #pragma unroll
    for (int i = 0; i < 32; i += 8) {
        float v = tile[threadIdx.x][threadIdx.y + i];
        __nv_bfloat16 hi = __float2bfloat16(v);
        __nv_bfloat16 lo = __float2bfloat16(v - __bfloat162float(hi));
        g_fT_hi[(size_t)(f2 + i) * N_ + n2] = hi;
        g_fT_lo[(size_t)(f2 + i) * N_ + n2] = lo;
    }
}

// ============================================================
// K_transpose: BT[z][g][f] = B[z][f][g]
// ============================================================
__global__ void k_transpose(const float* __restrict__ th,
                            const float* __restrict__ rp,
                            const float* __restrict__ np,
                            const float* __restrict__ ep)
{
    const int z = blockIdx.z;
    const float* src;
    if (z == 0)      src = th;
    else if (z < 17) src = rp + (size_t)(z - 1)  * F_ * F_;
    else if (z < 21) src = np + (size_t)(z - 17) * F_ * F_;
    else             src = ep + (size_t)(z - 21) * F_ * F_;
    float* dst = g_BT + (size_t)z * F_ * F_;

    __shared__ float tile[32][33];
    int x = blockIdx.x * 32 + threadIdx.x;
    int y = blockIdx.y * 32 + threadIdx.y;
    #pragma unroll
    for (int i = 0; i < 32; i += 8)
        tile[threadIdx.y + i][threadIdx.x] = src[(size_t)(y + i) * F_ + x];
    __syncthreads();
    int x2 = blockIdx.y * 32 + threadIdx.x;
    int y2 = blockIdx.x * 32 + threadIdx.y;
    #pragma unroll
    for (int i = 0; i < 32; i += 8)
        dst[(size_t)(y2 + i) * F_ + x2] = tile[threadIdx.x][threadIdx.y + i];
}

// ============================================================
// K_sort: stable counting sort by nmm + tile descriptors
// ============================================================
__global__ __launch_bounds__(256) void k_sort(const int* __restrict__ nmm)
{
    __shared__ int hist[4][256];
    __shared__ int basep[4][256];
    __shared__ int btot[4];
    __shared__ int boff[4];

    const int tid = threadIdx.x;
    const int r0 = tid * 16;
    int myb[16];
    int c[4] = {0, 0, 0, 0};
    #pragma unroll
    for (int i = 0; i < 16; i++) {
        int b = nmm[r0 + i];
        myb[i] = b;
        c[b]++;
    }
    #pragma unroll
    for (int b = 0; b < 4; b++) hist[b][tid] = c[b];
    __syncthreads();

    const int w = tid >> 5, lane = tid & 31;
    if (w < 4) {
        int b = w;
        int loc[8];
        int sum = 0;
        #pragma unroll
        for (int q = 0; q < 8; q++) {
            loc[q] = sum;
            sum += hist[b][lane * 8 + q];
        }
        int pre = sum;
        #pragma unroll
        for (int off = 1; off < 32; off <<= 1) {
            int v = __shfl_up_sync(0xffffffffu, pre, off);
            if (lane >= off) pre += v;
        }
        int tot = __shfl_sync(0xffffffffu, pre, 31);
        pre -= sum;
        #pragma unroll
        for (int q = 0; q < 8; q++) basep[b][lane * 8 + q] = pre + loc[q];
        if (lane == 31) btot[b] = tot;
    }
    __syncthreads();

    if (tid == 0) {
        int off = 0, t = 0;
        for (int b = 0; b < 4; b++) {
            boff[b] = off;
            int cnt = btot[b];
            for (int k = 0; k < cnt; k += 64) {
                g_tile_s[t] = b;
                g_tile_start[t] = off + k;
                g_tile_cnt[t] = min(64, cnt - k);
                t++;
            }
            off += cnt;
        }
        for (; t < MAXTILES; t++) { g_tile_cnt[t] = 0; g_tile_s[t] = 0; g_tile_start[t] = 0; }
    }
    __syncthreads();

    int pos[4];
    #pragma unroll
    for (int b = 0; b < 4; b++) pos[b] = boff[b] + basep[b][tid];
    #pragma unroll
    for (int i = 0; i < 16; i++) {
        int b = myb[i];
        g_perm[pos[b]++] = r0 + i;
    }
}

// ============================================================
// K1: g_feat = feature @ theta^T + b  (FFMA2)
// ============================================================
__global__ __launch_bounds__(256) void k1b(const float* __restrict__ feature,
                                           const float* __restrict__ bias)
{
    __shared__ float As[64][20];
    __shared__ float Bs[16][260];

    const int tid = threadIdx.x;
    const int base = blockIdx.x * 64;
    const int ty = tid >> 4, tx = tid & 15, r0 = ty << 2;
    const int lrow = tid >> 2, lq = (tid & 3) << 2;
    const int bRow = tid >> 4, bCol = (tid & 15) << 4;

    unsigned long long acc2[4][8];
    #pragma unroll
    for (int i = 0; i < 4; i++)
        #pragma unroll
        for (int k = 0; k < 8; k++) acc2[i][k] = 0ull;

    const float* Arow = feature + (size_t)(base + lrow) * F_;
    const float* BT = g_BT;

    for (int kb = 0; kb < F_; kb += 16) {
        float4 a4 = *(const float4*)(Arow + kb + lq);
        const float* bp = BT + (size_t)(kb + bRow) * F_ + bCol;
        float4 b0 = *(const float4*)(bp + 0);
        float4 b1 = *(const float4*)(bp + 4);
        float4 b2 = *(const float4*)(bp + 8);
        float4 b3 = *(const float4*)(bp + 12);
        __syncthreads();
        *(float4*)(&As[lrow][lq]) = a4;
        *(float4*)(&Bs[bRow][bCol + 0])  = b0;
        *(float4*)(&Bs[bRow][bCol + 4])  = b1;
        *(float4*)(&Bs[bRow][bCol + 8])  = b2;
        *(float4*)(&Bs[bRow][bCol + 12]) = b3;
        __syncthreads();

        #pragma unroll
        for (int kk = 0; kk < 16; kk++) {
            unsigned long long a2[4];
            #pragma unroll
            for (int i = 0; i < 4; i++) a2[i] = pack2(As[r0 + i][kk]);
            #pragma unroll
            for (int j4 = 0; j4 < 4; j4++) {
                ulonglong2 bv = *(const ulonglong2*)(&Bs[kk][(tx << 2) + (j4 << 6)]);
                #pragma unroll
                for (int i = 0; i < 4; i++) {
                    ffma2(acc2[i][j4 * 2 + 0], a2[i], bv.x);
                    ffma2(acc2[i][j4 * 2 + 1], a2[i], bv.y);
                }
            }
        }
    }

    #pragma unroll
    for (int i = 0; i < 4; i++) {
        float* ob = g_feat + (size_t)(base + r0 + i) * F_;
        #pragma unroll
        for (int j4 = 0; j4 < 4; j4++) {
            int col = (tx << 2) + (j4 << 6);
            float2 p0 = lo_hi(acc2[i][j4 * 2 + 0]);
            float2 p1 = lo_hi(acc2[i][j4 * 2 + 1]);
            float4 v = make_float4(p0.x + bias[col + 0], p0.y + bias[col + 1],
                                   p1.x + bias[col + 2], p1.y + bias[col + 3]);
            *(float4*)(ob + col) = v;
        }
    }
}

// ============================================================
// K_bgemm<MODE>: bucketed projection GEMMs (FFMA2)
// ============================================================
template<int MODE>
__global__ __launch_bounds__(256) void k_bgemm()
{
    const int t = blockIdx.x;
    const int cnt = g_tile_cnt[t];
    if (cnt == 0) return;
    const int s = g_tile_s[t];
    const int j = blockIdx.y;
    const int start = g_tile_start[t];

    __shared__ int idx[64];
    __shared__ float As[64][20];
    __shared__ float Bs[16][260];

    const int tid = threadIdx.x;
    if (tid < 64) idx[tid] = g_perm[start + min(tid, cnt - 1)];
    __syncthreads();

    const float* BT;
    if (MODE == 0)      BT = g_BT + (size_t)(1 + s * T_ + j) * F_ * F_;
    else if (MODE == 1) BT = g_BT + (size_t)(17 + s) * F_ * F_;
    else                BT = g_BT + (size_t)(21 + s * T_ + j) * F_ * F_;

    const int ty = tid >> 4, tx = tid & 15, r0 = ty << 2;
    const int lrow = tid >> 2, lq = (tid & 3) << 2;
    const int bRow = tid >> 4, bCol = (tid & 15) << 4;

    const int node_l = idx[lrow];
    const float* Arow;
    if (MODE == 2) Arow = g_edgefea + ((size_t)node_l * T_ + j) * F_;
    else           Arow = g_feat + (size_t)node_l * F_;

    unsigned long long acc2[4][8];
    #pragma unroll
    for (int i = 0; i < 4; i++)
        #pragma unroll
        for (int k = 0; k < 8; k++) acc2[i][k] = 0ull;

    for (int kb = 0; kb < F_; kb += 16) {
        float4 a4 = *(const float4*)(Arow + kb + lq);
        const float* bp = BT + (size_t)(kb + bRow) * F_ + bCol;
        float4 b0 = *(const float4*)(bp + 0);
        float4 b1 = *(const float4*)(bp + 4);
        float4 b2 = *(const float4*)(bp + 8);
        float4 b3 = *(const float4*)(bp + 12);
        __syncthreads();
        *(float4*)(&As[lrow][lq]) = a4;
        *(float4*)(&Bs[bRow][bCol + 0])  = b0;
        *(float4*)(&Bs[bRow][bCol + 4])  = b1;
        *(float4*)(&Bs[bRow][bCol + 8])  = b2;
        *(float4*)(&Bs[bRow][bCol + 12]) = b3;
        __syncthreads();

        #pragma unroll
        for (int kk = 0; kk < 16; kk++) {
            unsigned long long a2[4];
            #pragma unroll
            for (int i = 0; i < 4; i++) a2[i] = pack2(As[r0 + i][kk]);
            #pragma unroll
            for (int j4 = 0; j4 < 4; j4++) {
                ulonglong2 bv = *(const ulonglong2*)(&Bs[kk][(tx << 2) + (j4 << 6)]);
                #pragma unroll
                for (int i = 0; i < 4; i++) {
                    ffma2(acc2[i][j4 * 2 + 0], a2[i], bv.x);
                    ffma2(acc2[i][j4 * 2 + 1], a2[i], bv.y);
                }
            }
        }
    }

    if (MODE == 0) {
        #pragma unroll
        for (int i = 0; i < 4; i++) {
            int node = idx[r0 + i];
            const float* rr = g_recon + ((size_t)node * T_ + j) * F_;
            float part = 0.f;
            #pragma unroll
            for (int j4 = 0; j4 < 4; j4++) {
                int col = (tx << 2) + (j4 << 6);
                float2 p0 = lo_hi(acc2[i][j4 * 2 + 0]);
                float2 p1 = lo_hi(acc2[i][j4 * 2 + 1]);
                float4 rv = *(const float4*)(rr + col);
                float d0 = p0.x - rv.x, d1 = p0.y - rv.y;
                float d2 = p1.x - rv.z, d3 = p1.y - rv.w;
                part = fmaf(d0, d0, part); part = fmaf(d1, d1, part);
                part = fmaf(d2, d2, part); part = fmaf(d3, d3, part);
            }
            #pragma unroll
            for (int m = 8; m > 0; m >>= 1)
                part += __shfl_xor_sync(0xffffffffu, part, m);
            if (tx == 0 && (r0 + i) < cnt)
                g_rownorm[node * T_ + j] = sqrtf(part);
        }
    } else {
        #pragma unroll
        for (int i = 0; i < 4; i++) {
            if ((r0 + i) >= cnt) continue;
            int node = idx[r0 + i];
            float* ob;
            if (MODE == 1) ob = g_nodeproj + (size_t)node * F_;
            else           ob = g_edgeproj + ((size_t)node * T_ + j) * F_;
            #pragma unroll
            for (int j4 = 0; j4 < 4; j4++) {
                ulonglong2 v;
                v.x = acc2[i][j4 * 2 + 0];
                v.y = acc2[i][j4 * 2 + 1];
                *(ulonglong2*)(ob + (tx << 2) + (j4 << 6)) = v;
            }
        }
    }
}

// ============================================================
// K_attn
// ============================================================
__global__ __launch_bounds__(256) void k_attn(float* __restrict__ node_rep)
{
    const int i = blockIdx.x, tid = threadIdx.x;
    const int h = tid >> 5, lane = tid & 31;
    __shared__ float sw[T_][H_];

    float np = g_nodeproj[(size_t)i * F_ + tid];
    const float inv = rsqrtf((float)D_);

    #pragma unroll
    for (int t = 0; t < T_; t++) {
        float v = np * g_edgeproj[((size_t)i * T_ + t) * F_ + tid];
        #pragma unroll
        for (int off = 16; off > 0; off >>= 1)
            v += __shfl_down_sync(0xffffffffu, v, off);
        if (lane == 0) sw[t][h] = v * inv;
    }
    __syncthreads();

    if (tid < T_) {
        int t = tid;
        float mx = sw[t][0];
        #pragma unroll
        for (int hh = 1; hh < H_; hh++) mx = fmaxf(mx, sw[t][hh]);
        float sm = 0.f;
        #pragma unroll
        for (int hh = 0; hh < H_; hh++) {
            float e = expf(sw[t][hh] - mx);
            sw[t][hh] = e;
            sm += e;
        }
        float r = 1.f / sm;
        #pragma unroll
        for (int hh = 0; hh < H_; hh++) sw[t][hh] *= r;
    }
    __syncthreads();

    float rep = 0.f;
    #pragma unroll
    for (int t = 0; t < T_; t++)
        rep += fmaxf(sw[t][h] * g_edgefea[((size_t)i * T_ + t) * F_ + tid], 0.f);
    node_rep[(size_t)i * F_ + tid] = rep;
}

// ============================================================
// K_pred
// ============================================================
__global__ __launch_bounds__(256) void k_pred(const float* __restrict__ node_rep,
                                              const int* __restrict__ node_idx,
                                              const float* __restrict__ pw,
                                              const float* __restrict__ pb,
                                              float* __restrict__ predict)
{
    const int warp = threadIdx.x >> 5, lane = threadIdx.x & 31;
    const int p = blockIdx.x * 8 + warp;
    const float* a = node_rep + (size_t)node_idx[p] * F_;

    float part[C_];
    #pragma unroll
    for (int c = 0; c < C_; c++) part[c] = 0.f;
    for (int f = lane; f < F_; f += 32) {
        float av = a[f];
        #pragma unroll
        for (int c = 0; c < C_; c++)
            part[c] = fmaf(av, pw[c * F_ + f], part[c]);
    }
    #pragma unroll
    for (int c = 0; c < C_; c++)
        #pragma unroll
        for (int off = 16; off > 0; off >>= 1)
            part[c] += __shfl_down_sync(0xffffffffu, part[c], off);

    if (lane == 0) {
        float sig[C_];
        float mx = -1e30f;
        #pragma unroll
        for (int c = 0; c < C_; c++) {
            float l = part[c] + pb[c];
            float sg = 1.f / (1.f + expf(-l));
            sig[c] = sg;
            mx = fmaxf(mx, sg);
        }
        float sm = 0.f;
        #pragma unroll
        for (int c = 0; c < C_; c++) {
            float e = expf(sig[c] - mx);
            sig[c] = e;
            sm += e;
        }
        float r = 1.f / sm;
        #pragma unroll
        for (int c = 0; c < C_; c++)
            predict[(size_t)p * C_ + c] = sig[c] * r;
    }
}

// ============================================================
// K_reduce: loss
// ============================================================
__global__ __launch_bounds__(256) void k_reduce(float* __restrict__ lossOut)
{
    __shared__ float s1[256], s2[256], s3[256];
    int tid = threadIdx.x;
    float l1 = 0.f, l2 = 0.f, re = 0.f;
    for (int i = tid; i < NT_; i += 256) {
        l1 += g_rowsum[i];
        l2 += sqrtf(g_rowsumsq[i]);
        re += g_rownorm[i];
    }
    s1[tid] = l1; s2[tid] = l2; s3[tid] = re;
    __syncthreads();
    for (int off = 128; off > 0; off >>= 1) {
        if (tid < off) {
            s1[tid] += s1[tid + off];
            s2[tid] += s2[tid + off];
            s3[tid] += s3[tid + off];
        }
        __syncthreads();
    }
    if (tid == 0)
        lossOut[0] = 0.1f * (0.01f * s3[0] + 0.2f * s2[0] + s1[0]);
}

// ============================================================
extern "C" void kernel_launch(void* const* d_in, const int* in_sizes, int n_in,
                              void* d_out, int out_size)
{
    (void)in_sizes; (void)n_in; (void)out_size;
    const float* feature  = (const float*)d_in[0];
    const float* mask     = (const float*)d_in[1];
    const int*   nmm      = (const int*)  d_in[2];
    const int*   node_idx = (const int*)  d_in[3];
    const float* theta_w  = (const float*)d_in[4];
    const float* theta_b  = (const float*)d_in[5];
    const float* linear   = (const float*)d_in[6];
    const float* rp       = (const float*)d_in[7];
    const float* mhnp     = (const float*)d_in[8];
    const float* mhep     = (const float*)d_in[9];
    const float* pw       = (const float*)d_in[10];
    const float* pb       = (const float*)d_in[11];

    float* out      = (float*)d_out;
    float* predict  = out;
    float* loss     = out + P_ * C_;
    float* node_rep = out + P_ * C_ + 1;

    cudaFuncSetAttribute(k2_mma, cudaFuncAttributeMaxDynamicSharedMemorySize, SMEM_K2);

    k_transpose<<<dim3(8, 8, 37), dim3(32, 8)>>>(theta_w, rp, mhnp, mhep);
    k_sort<<<1, 256>>>(nmm);
    k1b<<<N_ / 64, 256>>>(feature, theta_b);
    k_featT<<<dim3(8, 128), dim3(32, 8)>>>();
    k2_mma<<<NT_ / BM, 512, SMEM_K2>>>(linear, mask);
    k_bgemm<0><<<dim3(MAXTILES, T_), 256>>>();
    k_bgemm<1><<<dim3(MAXTILES, 1), 256>>>();
    k_bgemm<2><<<dim3(MAXTILES, T_), 256>>>();
    k_attn<<<N_, 256>>>(node_rep);
    k_pred<<<P_ / 8, 256>>>(node_rep, node_idx, pw, pb, predict);
    k_reduce<<<1, 256>>>(loss);
}

// round 5
// speedup vs baseline: 3.9645x; 1.1454x over previous
#include <cuda_runtime.h>
#include <cuda_bf16.h>
#include <math.h>
#include <stdint.h>

#define N_ 4096
#define T_ 4
#define F_ 256
#define H_ 8
#define C_ 16
#define P_ 1024
#define D_ 32
#define NT_ (N_*T_)
#define MAXTILES 67

#define BM 128
#define BK 32
#define NCHUNK (N_/BK)
#define APAD 40
#define BPAD 40

// k2_mma dynamic smem offsets (bytes)
#define OFF_A(s,hl)  (((s)*2+(hl)) * (BM*APAD*2))
#define OFF_B(s,hl)  (40960 + ((s)*2+(hl)) * (256*BPAD*2))
#define OFF_RS       122880
#define OFF_RQ       (122880+2048)
#define OFF_RINV     (122880+4096)
#define SMEM_K2      (122880+4096+512+128)

// k_gemm_tc dynamic smem offsets (bytes): M=64 tile
#define GA(s,hl)     (((s)*2+(hl)) * (64*APAD*2))
#define GB(s,hl)     (20480 + ((s)*2+(hl)) * (256*BPAD*2))
#define GIDX         102400
#define GRED         102656
#define SMEM_G       103936
#define GKCH         (F_/BK)

// ---- scratch (static device globals) ----
__device__ float g_feat[N_*F_];
__device__ float g_recon[NT_*F_];
__device__ float g_edgefea[NT_*F_];
__device__ float g_nodeproj[N_*F_];
__device__ float g_edgeproj[NT_*F_];
__device__ float g_rowsum[NT_];
__device__ float g_rowsumsq[NT_];
__device__ float g_rownorm[NT_];
__device__ int   g_perm[N_];
__device__ int   g_tile_s[MAXTILES];
__device__ int   g_tile_start[MAXTILES];
__device__ int   g_tile_cnt[MAXTILES];
__device__ __align__(16) __nv_bfloat16 g_fT_hi[F_*N_];
__device__ __align__(16) __nv_bfloat16 g_fT_lo[F_*N_];
// weights bf16 hi/lo: [0]=theta, [1..16]=rp, [17..20]=mhnp, [21..36]=mhep
__device__ __align__(16) __nv_bfloat16 g_Whi[37*F_*F_];
__device__ __align__(16) __nv_bfloat16 g_Wlo[37*F_*F_];

// ---- mma.sync / ldmatrix / cp.async helpers ----
__device__ __forceinline__ uint32_t smem_u32(const void* p) {
    uint32_t a;
    asm("{ .reg .u64 t; cvta.to.shared.u64 t, %1; cvt.u32.u64 %0, t; }"
        : "=r"(a) : "l"(p));
    return a;
}
__device__ __forceinline__ void ldm_x4(uint32_t* r, uint32_t addr) {
    asm volatile("ldmatrix.sync.aligned.m8n8.x4.shared.b16 {%0,%1,%2,%3}, [%4];"
                 : "=r"(r[0]), "=r"(r[1]), "=r"(r[2]), "=r"(r[3]) : "r"(addr));
}
__device__ __forceinline__ void mma_bf16(float* d, const uint32_t* a,
                                         uint32_t b0, uint32_t b1) {
    asm volatile("mma.sync.aligned.m16n8k16.row.col.f32.bf16.bf16.f32 "
                 "{%0,%1,%2,%3}, {%4,%5,%6,%7}, {%8,%9}, {%0,%1,%2,%3};"
                 : "+f"(d[0]), "+f"(d[1]), "+f"(d[2]), "+f"(d[3])
                 : "r"(a[0]), "r"(a[1]), "r"(a[2]), "r"(a[3]), "r"(b0), "r"(b1));
}
__device__ __forceinline__ void cpa16(uint32_t dst, const void* src) {
    asm volatile("cp.async.ca.shared.global [%0], [%1], 16;" :: "r"(dst), "l"(src));
}
#define CP_COMMIT() asm volatile("cp.async.commit_group;" ::: "memory")
#define CP_WAIT0()  asm volatile("cp.async.wait_group 0;"  ::: "memory")

// ls generation + bf16 hi/lo pack (8 values)
__device__ __forceinline__ void pack_ls(const float* lp, const float* mp,
                                        float& psum, float& psq,
                                        uint32_t* Ah, uint32_t* Al)
{
    float4 L0 = *(const float4*)lp;
    float4 L1 = *(const float4*)(lp + 4);
    float4 M0 = *(const float4*)mp;
    float4 M1 = *(const float4*)(mp + 4);
    float v[8];
    v[0] = fmaxf(L0.x * M0.x, 0.f); v[1] = fmaxf(L0.y * M0.y, 0.f);
    v[2] = fmaxf(L0.z * M0.z, 0.f); v[3] = fmaxf(L0.w * M0.w, 0.f);
    v[4] = fmaxf(L1.x * M1.x, 0.f); v[5] = fmaxf(L1.y * M1.y, 0.f);
    v[6] = fmaxf(L1.z * M1.z, 0.f); v[7] = fmaxf(L1.w * M1.w, 0.f);
    #pragma unroll
    for (int i = 0; i < 8; i++) { psum += v[i]; psq = fmaf(v[i], v[i], psq); }
    #pragma unroll
    for (int p = 0; p < 4; p++) {
        __nv_bfloat162 hp = __floats2bfloat162_rn(v[2*p], v[2*p+1]);
        float r0 = v[2*p]   - __bfloat162float(hp.x);
        float r1 = v[2*p+1] - __bfloat162float(hp.y);
        __nv_bfloat162 lw = __floats2bfloat162_rn(r0, r1);
        Ah[p] = *(uint32_t*)&hp;
        Al[p] = *(uint32_t*)&lw;
    }
}

// plain hi/lo split of 8 fp32
__device__ __forceinline__ void split8(const float* p, uint32_t* Ah, uint32_t* Al)
{
    float4 a = *(const float4*)p;
    float4 b = *(const float4*)(p + 4);
    float v[8] = {a.x, a.y, a.z, a.w, b.x, b.y, b.z, b.w};
    #pragma unroll
    for (int q = 0; q < 4; q++) {
        __nv_bfloat162 hp = __floats2bfloat162_rn(v[2*q], v[2*q+1]);
        float r0 = v[2*q]   - __bfloat162float(hp.x);
        float r1 = v[2*q+1] - __bfloat162float(hp.y);
        __nv_bfloat162 lw = __floats2bfloat162_rn(r0, r1);
        Ah[q] = *(uint32_t*)&hp;
        Al[q] = *(uint32_t*)&lw;
    }
}

// ============================================================
// K2-MMA (unchanged from round 4): recon = ls @ feat, fused.
// ============================================================
__global__ __launch_bounds__(512, 1) void k2_mma(const float* __restrict__ linear,
                                                 const float* __restrict__ mask)
{
    extern __shared__ char sm[];
    const uint32_t sb = smem_u32(sm);
    const int tid = threadIdx.x;
    const int wid = tid >> 5, lane = tid & 31;
    const int warp_m = wid & 3, warp_n = wid >> 2;
    const int ntBase = blockIdx.x * BM;

    const int arow = tid >> 2;
    const int akof = (tid & 3) * 8;
    const float* lptr = linear + (size_t)(ntBase + arow) * N_ + akof;
    const float* mptr = mask   + (size_t)(ntBase + arow) * N_ + akof;
    const uint32_t aSt = (uint32_t)(arow * APAD + akof) * 2;

    const int bhl = tid >> 8;
    const int bn  = tid & 255;
    const char* bsrc = (const char*)((bhl ? g_fT_lo : g_fT_hi) + (size_t)bn * N_);
    const uint32_t bSt = (uint32_t)(bn * BPAD) * 2;

    float psum = 0.f, psq = 0.f;
    uint32_t Ah[4], Al[4];

    const int aRowL = warp_m * 32 + (lane & 7) + ((lane >> 3) & 1) * 8;
    const int aColL = (lane >> 4) * 8;
    const int bRowL = warp_n * 64 + (lane & 7) + ((lane >> 4) & 1) * 8;
    const int bColL = ((lane >> 3) & 1) * 8;

    pack_ls(lptr, mptr, psum, psq, Ah, Al);
    {
        uint32_t d = sb + OFF_B(0, bhl) + bSt;
        #pragma unroll
        for (int q = 0; q < 4; q++) cpa16(d + q * 16, bsrc + q * 16);
    }
    CP_COMMIT(); CP_WAIT0();
    __syncthreads();
    *(uint4*)(sm + OFF_A(0,0) + aSt) = make_uint4(Ah[0], Ah[1], Ah[2], Ah[3]);
    *(uint4*)(sm + OFF_A(0,1) + aSt) = make_uint4(Al[0], Al[1], Al[2], Al[3]);
    __syncthreads();

    float acc[2][8][4];
    #pragma unroll
    for (int i = 0; i < 2; i++)
        #pragma unroll
        for (int j = 0; j < 8; j++)
            #pragma unroll
            for (int q = 0; q < 4; q++) acc[i][j][q] = 0.f;

    for (int c = 0; c < NCHUNK; c++) {
        const int s = c & 1;
        if (c + 1 < NCHUNK) {
            uint32_t d = sb + OFF_B(s ^ 1, bhl) + bSt;
            const char* src = bsrc + (size_t)(c + 1) * BK * 2;
            #pragma unroll
            for (int q = 0; q < 4; q++) cpa16(d + q * 16, src + q * 16);
            CP_COMMIT();
            pack_ls(lptr + (c + 1) * BK, mptr + (c + 1) * BK, psum, psq, Ah, Al);
        }

        const uint32_t aHi = sb + OFF_A(s,0), aLo = sb + OFF_A(s,1);
        const uint32_t bHi = sb + OFF_B(s,0), bLo = sb + OFF_B(s,1);

        #pragma unroll
        for (int ks = 0; ks < BK; ks += 16) {
            uint32_t ah[2][4], alr[2][4], bb[4][4];
            ldm_x4(ah[0], aHi + (uint32_t)((aRowL)      * APAD + ks + aColL) * 2);
            ldm_x4(ah[1], aHi + (uint32_t)((aRowL + 16) * APAD + ks + aColL) * 2);
            #pragma unroll
            for (int g = 0; g < 4; g++)
                ldm_x4(bb[g], bHi + (uint32_t)((bRowL + g * 16) * BPAD + ks + bColL) * 2);
            #pragma unroll
            for (int mf = 0; mf < 2; mf++)
                #pragma unroll
                for (int nf = 0; nf < 8; nf++)
                    mma_bf16(acc[mf][nf], ah[mf],
                             bb[nf >> 1][(nf & 1) * 2], bb[nf >> 1][(nf & 1) * 2 + 1]);
            ldm_x4(alr[0], aLo + (uint32_t)((aRowL)      * APAD + ks + aColL) * 2);
            ldm_x4(alr[1], aLo + (uint32_t)((aRowL + 16) * APAD + ks + aColL) * 2);
            #pragma unroll
            for (int mf = 0; mf < 2; mf++)
                #pragma unroll
                for (int nf = 0; nf < 8; nf++)
                    mma_bf16(acc[mf][nf], alr[mf],
                             bb[nf >> 1][(nf & 1) * 2], bb[nf >> 1][(nf & 1) * 2 + 1]);
            #pragma unroll
            for (int g = 0; g < 4; g++)
                ldm_x4(bb[g], bLo + (uint32_t)((bRowL + g * 16) * BPAD + ks + bColL) * 2);
            #pragma unroll
            for (int mf = 0; mf < 2; mf++)
                #pragma unroll
                for (int nf = 0; nf < 8; nf++)
                    mma_bf16(acc[mf][nf], ah[mf],
                             bb[nf >> 1][(nf & 1) * 2], bb[nf >> 1][(nf & 1) * 2 + 1]);
        }

        if (c + 1 < NCHUNK) {
            CP_WAIT0();
            __syncthreads();
            *(uint4*)(sm + OFF_A(s^1,0) + aSt) = make_uint4(Ah[0], Ah[1], Ah[2], Ah[3]);
            *(uint4*)(sm + OFF_A(s^1,1) + aSt) = make_uint4(Al[0], Al[1], Al[2], Al[3]);
            __syncthreads();
        }
    }

    ((float*)(sm + OFF_RS))[arow * 4 + (tid & 3)] = psum;
    ((float*)(sm + OFF_RQ))[arow * 4 + (tid & 3)] = psq;
    __syncthreads();
    if (tid < BM) {
        const float* rs = (const float*)(sm + OFF_RS) + tid * 4;
        const float* rq = (const float*)(sm + OFF_RQ) + tid * 4;
        float ss = (rs[0] + rs[1]) + (rs[2] + rs[3]);
        float sq = (rq[0] + rq[1]) + (rq[2] + rq[3]);
        g_rowsum[ntBase + tid]   = ss;
        g_rowsumsq[ntBase + tid] = sq;
        ((float*)(sm + OFF_RINV))[tid] = 1.f / (ss + 1.f);
    }
    __syncthreads();
    const float* rinv = (const float*)(sm + OFF_RINV);

    #pragma unroll
    for (int mf = 0; mf < 2; mf++) {
        #pragma unroll
        for (int half = 0; half < 2; half++) {
            int row = warp_m * 32 + mf * 16 + half * 8 + (lane >> 2);
            int nt = ntBase + row;
            float inv = rinv[row];
            const float* fb = g_feat + (size_t)(nt >> 2) * F_;
            float* rb = g_recon   + (size_t)nt * F_;
            float* eb = g_edgefea + (size_t)nt * F_;
            #pragma unroll
            for (int nf = 0; nf < 8; nf++) {
                int col = warp_n * 64 + nf * 8 + (lane & 3) * 2;
                float d0 = acc[mf][nf][half * 2];
                float d1 = acc[mf][nf][half * 2 + 1];
                *(float2*)(rb + col) = make_float2(d0, d1);
                float2 fv = *(const float2*)(fb + col);
                *(float2*)(eb + col) = make_float2((d0 + fv.x) * inv, (d1 + fv.y) * inv);
            }
        }
    }
}

// ============================================================
// K_gemm_tc<MODE>: tensor-core GEMM, M-tile 64, N=256, K=256.
//  MODE 0: inp_proj diff -> rownorm   (A=feat[perm],      B=rp[s,j])
//  MODE 1: node_projd                 (A=feat[perm],      B=mhnp[s])
//  MODE 2: edge_projd                 (A=edgefea[perm,j], B=mhep[s,j])
//  MODE 3: feature@theta^T + bias     (A=Ain dense,       B=theta)
// ============================================================
template<int MODE>
__global__ __launch_bounds__(256, 1) void k_gemm_tc(const float* __restrict__ Ain,
                                                    const float* __restrict__ bias)
{
    extern __shared__ char sm[];
    const uint32_t sb = smem_u32(sm);
    const int tid = threadIdx.x;
    const int wid = tid >> 5, lane = tid & 31;
    const int warp_m = wid & 1, warp_n = wid >> 1;

    int s = 0, j = 0, cnt = 64, mBase = 0;
    int* sidx = (int*)(sm + GIDX);
    if (MODE == 3) {
        mBase = blockIdx.x * 64;
    } else {
        const int t = blockIdx.x;
        cnt = g_tile_cnt[t];
        if (cnt == 0) return;
        s = g_tile_s[t];
        j = blockIdx.y;
        const int start = g_tile_start[t];
        if (tid < 64) sidx[tid] = g_perm[start + min(tid, cnt - 1)];
        __syncthreads();
    }

    // A producer
    const int arow = tid >> 2;
    const int akof = (tid & 3) * 8;
    const float* aptr;
    if (MODE == 3)      aptr = Ain + (size_t)(mBase + arow) * F_ + akof;
    else if (MODE == 2) aptr = g_edgefea + ((size_t)sidx[arow] * T_ + j) * F_ + akof;
    else                aptr = g_feat + (size_t)sidx[arow] * F_ + akof;
    const uint32_t aSt = (uint32_t)(arow * APAD + akof) * 2;

    // B producer: weight row n = tid (256 rows), K-chunks of 32
    int z;
    if (MODE == 3)      z = 0;
    else if (MODE == 0) z = 1 + s * T_ + j;
    else if (MODE == 1) z = 17 + s;
    else                z = 21 + s * T_ + j;
    const char* bh_src = (const char*)(g_Whi + (size_t)z * F_ * F_ + (size_t)tid * F_);
    const char* bl_src = (const char*)(g_Wlo + (size_t)z * F_ * F_ + (size_t)tid * F_);
    const uint32_t bSt = (uint32_t)(tid * BPAD) * 2;

    const int aRowL = warp_m * 32 + (lane & 7) + ((lane >> 3) & 1) * 8;
    const int aColL = (lane >> 4) * 8;
    const int bRowL = warp_n * 64 + (lane & 7) + ((lane >> 4) & 1) * 8;
    const int bColL = ((lane >> 3) & 1) * 8;

    uint32_t Ah[4], Al[4];
    split8(aptr, Ah, Al);
    {
        uint32_t dh = sb + GB(0,0) + bSt;
        uint32_t dl = sb + GB(0,1) + bSt;
        #pragma unroll
        for (int q = 0; q < 4; q++) {
            cpa16(dh + q * 16, bh_src + q * 16);
            cpa16(dl + q * 16, bl_src + q * 16);
        }
    }
    CP_COMMIT(); CP_WAIT0();
    __syncthreads();
    *(uint4*)(sm + GA(0,0) + aSt) = make_uint4(Ah[0], Ah[1], Ah[2], Ah[3]);
    *(uint4*)(sm + GA(0,1) + aSt) = make_uint4(Al[0], Al[1], Al[2], Al[3]);
    __syncthreads();

    float acc[2][8][4];
    #pragma unroll
    for (int i = 0; i < 2; i++)
        #pragma unroll
        for (int q = 0; q < 8; q++)
            #pragma unroll
            for (int e = 0; e < 4; e++) acc[i][q][e] = 0.f;

    for (int c = 0; c < GKCH; c++) {
        const int st = c & 1;
        if (c + 1 < GKCH) {
            uint32_t dh = sb + GB(st ^ 1, 0) + bSt;
            uint32_t dl = sb + GB(st ^ 1, 1) + bSt;
            const char* sh = bh_src + (size_t)(c + 1) * BK * 2;
            const char* sl = bl_src + (size_t)(c + 1) * BK * 2;
            #pragma unroll
            for (int q = 0; q < 4; q++) {
                cpa16(dh + q * 16, sh + q * 16);
                cpa16(dl + q * 16, sl + q * 16);
            }
            CP_COMMIT();
            split8(aptr + (c + 1) * BK, Ah, Al);
        }

        const uint32_t aHi = sb + GA(st,0), aLo = sb + GA(st,1);
        const uint32_t bHi = sb + GB(st,0), bLo = sb + GB(st,1);

        #pragma unroll
        for (int ks = 0; ks < BK; ks += 16) {
            uint32_t ah[2][4], alr[2][4], bb[4][4];
            ldm_x4(ah[0], aHi + (uint32_t)((aRowL)      * APAD + ks + aColL) * 2);
            ldm_x4(ah[1], aHi + (uint32_t)((aRowL + 16) * APAD + ks + aColL) * 2);
            #pragma unroll
            for (int g = 0; g < 4; g++)
                ldm_x4(bb[g], bHi + (uint32_t)((bRowL + g * 16) * BPAD + ks + bColL) * 2);
            #pragma unroll
            for (int mf = 0; mf < 2; mf++)
                #pragma unroll
                for (int nf = 0; nf < 8; nf++)
                    mma_bf16(acc[mf][nf], ah[mf],
                             bb[nf >> 1][(nf & 1) * 2], bb[nf >> 1][(nf & 1) * 2 + 1]);
            ldm_x4(alr[0], aLo + (uint32_t)((aRowL)      * APAD + ks + aColL) * 2);
            ldm_x4(alr[1], aLo + (uint32_t)((aRowL + 16) * APAD + ks + aColL) * 2);
            #pragma unroll
            for (int mf = 0; mf < 2; mf++)
                #pragma unroll
                for (int nf = 0; nf < 8; nf++)
                    mma_bf16(acc[mf][nf], alr[mf],
                             bb[nf >> 1][(nf & 1) * 2], bb[nf >> 1][(nf & 1) * 2 + 1]);
            #pragma unroll
            for (int g = 0; g < 4; g++)
                ldm_x4(bb[g], bLo + (uint32_t)((bRowL + g * 16) * BPAD + ks + bColL) * 2);
            #pragma unroll
            for (int mf = 0; mf < 2; mf++)
                #pragma unroll
                for (int nf = 0; nf < 8; nf++)
                    mma_bf16(acc[mf][nf], ah[mf],
                             bb[nf >> 1][(nf & 1) * 2], bb[nf >> 1][(nf & 1) * 2 + 1]);
        }

        if (c + 1 < GKCH) {
            CP_WAIT0();
            __syncthreads();
            *(uint4*)(sm + GA(st^1,0) + aSt) = make_uint4(Ah[0], Ah[1], Ah[2], Ah[3]);
            *(uint4*)(sm + GA(st^1,1) + aSt) = make_uint4(Al[0], Al[1], Al[2], Al[3]);
            __syncthreads();
        }
    }

    // ---- epilogues ----
    if (MODE == 0) {
        float* sred = (float*)(sm + GRED);
        #pragma unroll
        for (int mf = 0; mf < 2; mf++) {
            #pragma unroll
            for (int half = 0; half < 2; half++) {
                int row = warp_m * 32 + mf * 16 + half * 8 + (lane >> 2);
                int node = sidx[row];
                const float* rr = g_recon + ((size_t)node * T_ + j) * F_;
                float part = 0.f;
                #pragma unroll
                for (int nf = 0; nf < 8; nf++) {
                    int col = warp_n * 64 + nf * 8 + (lane & 3) * 2;
                    float2 rv = *(const float2*)(rr + col);
                    float d0 = acc[mf][nf][half * 2]     - rv.x;
                    float d1 = acc[mf][nf][half * 2 + 1] - rv.y;
                    part = fmaf(d0, d0, part);
                    part = fmaf(d1, d1, part);
                }
                part += __shfl_xor_sync(0xffffffffu, part, 1);
                part += __shfl_xor_sync(0xffffffffu, part, 2);
                if ((lane & 3) == 0) sred[row * 4 + warp_n] = part;
            }
        }
        __syncthreads();
        if (tid < 64) {
            const float* r4 = sred + tid * 4;
            float tot = (r4[0] + r4[1]) + (r4[2] + r4[3]);
            if (tid < cnt)
                g_rownorm[sidx[tid] * T_ + j] = sqrtf(tot);
        }
    } else {
        #pragma unroll
        for (int mf = 0; mf < 2; mf++) {
            #pragma unroll
            for (int half = 0; half < 2; half++) {
                int row = warp_m * 32 + mf * 16 + half * 8 + (lane >> 2);
                float* ob;
                if (MODE == 3) {
                    ob = g_feat + (size_t)(mBase + row) * F_;
                } else {
                    if (row >= cnt) continue;
                    int node = sidx[row];
                    if (MODE == 1) ob = g_nodeproj + (size_t)node * F_;
                    else           ob = g_edgeproj + ((size_t)node * T_ + j) * F_;
                }
                #pragma unroll
                for (int nf = 0; nf < 8; nf++) {
                    int col = warp_n * 64 + nf * 8 + (lane & 3) * 2;
                    float d0 = acc[mf][nf][half * 2];
                    float d1 = acc[mf][nf][half * 2 + 1];
                    if (MODE == 3) {
                        d0 += bias[col];
                        d1 += bias[col + 1];
                    }
                    *(float2*)(ob + col) = make_float2(d0, d1);
                }
            }
        }
    }
}

// ============================================================
// K_wconv: weights fp32 -> bf16 hi/lo (no transpose needed)
// ============================================================
__global__ __launch_bounds__(256) void k_wconv(const float* __restrict__ th,
                                               const float* __restrict__ rp,
                                               const float* __restrict__ np,
                                               const float* __restrict__ ep)
{
    int i = blockIdx.x * 256 + threadIdx.x;
    int z = i >> 16;
    int off = i & 65535;
    const float* src;
    if (z == 0)      src = th;
    else if (z < 17) src = rp + (size_t)(z - 1)  * 65536;
    else if (z < 21) src = np + (size_t)(z - 17) * 65536;
    else             src = ep + (size_t)(z - 21) * 65536;
    float v = src[off];
    __nv_bfloat16 hi = __float2bfloat16(v);
    __nv_bfloat16 lo = __float2bfloat16(v - __bfloat162float(hi));
    g_Whi[i] = hi;
    g_Wlo[i] = lo;
}

// ============================================================
// K_featT: featT hi/lo bf16 [F_][N_] from g_feat
// ============================================================
__global__ void k_featT()
{
    __shared__ float tile[32][33];
    int x = blockIdx.x * 32 + threadIdx.x;
    int y = blockIdx.y * 32 + threadIdx.y;
    #pragma unroll
    for (int i = 0; i < 32; i += 8)
        tile[threadIdx.y + i][threadIdx.x] = g_feat[(size_t)(y + i) * F_ + x];
    __syncthreads();
    int f2 = blockIdx.x * 32 + threadIdx.y;
    int n2 = blockIdx.y * 32 + threadIdx.x;
    #pragma unroll
    for (int i = 0; i < 32; i += 8) {
        float v = tile[threadIdx.x][threadIdx.y + i];
        __nv_bfloat16 hi = __float2bfloat16(v);
        __nv_bfloat16 lo = __float2bfloat16(v - __bfloat162float(hi));
        g_fT_hi[(size_t)(f2 + i) * N_ + n2] = hi;
        g_fT_lo[(size_t)(f2 + i) * N_ + n2] = lo;
    }
}

// ============================================================
// K_sort: stable counting sort by nmm + tile descriptors
// ============================================================
__global__ __launch_bounds__(256) void k_sort(const int* __restrict__ nmm)
{
    __shared__ int hist[4][256];
    __shared__ int basep[4][256];
    __shared__ int btot[4];
    __shared__ int boff[4];

    const int tid = threadIdx.x;
    const int r0 = tid * 16;
    int myb[16];
    int c[4] = {0, 0, 0, 0};
    #pragma unroll
    for (int i = 0; i < 16; i++) {
        int b = nmm[r0 + i];
        myb[i] = b;
        c[b]++;
    }
    #pragma unroll
    for (int b = 0; b < 4; b++) hist[b][tid] = c[b];
    __syncthreads();

    const int w = tid >> 5, lane = tid & 31;
    if (w < 4) {
        int b = w;
        int loc[8];
        int sum = 0;
        #pragma unroll
        for (int q = 0; q < 8; q++) {
            loc[q] = sum;
            sum += hist[b][lane * 8 + q];
        }
        int pre = sum;
        #pragma unroll
        for (int off = 1; off < 32; off <<= 1) {
            int v = __shfl_up_sync(0xffffffffu, pre, off);
            if (lane >= off) pre += v;
        }
        int tot = __shfl_sync(0xffffffffu, pre, 31);
        pre -= sum;
        #pragma unroll
        for (int q = 0; q < 8; q++) basep[b][lane * 8 + q] = pre + loc[q];
        if (lane == 31) btot[b] = tot;
    }
    __syncthreads();

    if (tid == 0) {
        int off = 0, t = 0;
        for (int b = 0; b < 4; b++) {
            boff[b] = off;
            int cnt = btot[b];
            for (int k = 0; k < cnt; k += 64) {
                g_tile_s[t] = b;
                g_tile_start[t] = off + k;
                g_tile_cnt[t] = min(64, cnt - k);
                t++;
            }
            off += cnt;
        }
        for (; t < MAXTILES; t++) { g_tile_cnt[t] = 0; g_tile_s[t] = 0; g_tile_start[t] = 0; }
    }
    __syncthreads();

    int pos[4];
    #pragma unroll
    for (int b = 0; b < 4; b++) pos[b] = boff[b] + basep[b][tid];
    #pragma unroll
    for (int i = 0; i < 16; i++) {
        int b = myb[i];
        g_perm[pos[b]++] = r0 + i;
    }
}

// ============================================================
// K_attn
// ============================================================
__global__ __launch_bounds__(256) void k_attn(float* __restrict__ node_rep)
{
    const int i = blockIdx.x, tid = threadIdx.x;
    const int h = tid >> 5, lane = tid & 31;
    __shared__ float sw[T_][H_];

    float np = g_nodeproj[(size_t)i * F_ + tid];
    const float inv = rsqrtf((float)D_);

    #pragma unroll
    for (int t = 0; t < T_; t++) {
        float v = np * g_edgeproj[((size_t)i * T_ + t) * F_ + tid];
        #pragma unroll
        for (int off = 16; off > 0; off >>= 1)
            v += __shfl_down_sync(0xffffffffu, v, off);
        if (lane == 0) sw[t][h] = v * inv;
    }
    __syncthreads();

    if (tid < T_) {
        int t = tid;
        float mx = sw[t][0];
        #pragma unroll
        for (int hh = 1; hh < H_; hh++) mx = fmaxf(mx, sw[t][hh]);
        float sm = 0.f;
        #pragma unroll
        for (int hh = 0; hh < H_; hh++) {
            float e = expf(sw[t][hh] - mx);
            sw[t][hh] = e;
            sm += e;
        }
        float r = 1.f / sm;
        #pragma unroll
        for (int hh = 0; hh < H_; hh++) sw[t][hh] *= r;
    }
    __syncthreads();

    float rep = 0.f;
    #pragma unroll
    for (int t = 0; t < T_; t++)
        rep += fmaxf(sw[t][h] * g_edgefea[((size_t)i * T_ + t) * F_ + tid], 0.f);
    node_rep[(size_t)i * F_ + tid] = rep;
}

// ============================================================
// K_pred
// ============================================================
__global__ __launch_bounds__(256) void k_pred(const float* __restrict__ node_rep,
                                              const int* __restrict__ node_idx,
                                              const float* __restrict__ pw,
                                              const float* __restrict__ pb,
                                              float* __restrict__ predict)
{
    const int warp = threadIdx.x >> 5, lane = threadIdx.x & 31;
    const int p = blockIdx.x * 8 + warp;
    const float* a = node_rep + (size_t)node_idx[p] * F_;

    float part[C_];
    #pragma unroll
    for (int c = 0; c < C_; c++) part[c] = 0.f;
    for (int f = lane; f < F_; f += 32) {
        float av = a[f];
        #pragma unroll
        for (int c = 0; c < C_; c++)
            part[c] = fmaf(av, pw[c * F_ + f], part[c]);
    }
    #pragma unroll
    for (int c = 0; c < C_; c++)
        #pragma unroll
        for (int off = 16; off > 0; off >>= 1)
            part[c] += __shfl_down_sync(0xffffffffu, part[c], off);

    if (lane == 0) {
        float sig[C_];
        float mx = -1e30f;
        #pragma unroll
        for (int c = 0; c < C_; c++) {
            float l = part[c] + pb[c];
            float sg = 1.f / (1.f + expf(-l));
            sig[c] = sg;
            mx = fmaxf(mx, sg);
        }
        float sm = 0.f;
        #pragma unroll
        for (int c = 0; c < C_; c++) {
            float e = expf(sig[c] - mx);
            sig[c] = e;
            sm += e;
        }
        float r = 1.f / sm;
        #pragma unroll
        for (int c = 0; c < C_; c++)
            predict[(size_t)p * C_ + c] = sig[c] * r;
    }
}

// ============================================================
// K_reduce: loss
// ============================================================
__global__ __launch_bounds__(256) void k_reduce(float* __restrict__ lossOut)
{
    __shared__ float s1[256], s2[256], s3[256];
    int tid = threadIdx.x;
    float l1 = 0.f, l2 = 0.f, re = 0.f;
    for (int i = tid; i < NT_; i += 256) {
        l1 += g_rowsum[i];
        l2 += sqrtf(g_rowsumsq[i]);
        re += g_rownorm[i];
    }
    s1[tid] = l1; s2[tid] = l2; s3[tid] = re;
    __syncthreads();
    for (int off = 128; off > 0; off >>= 1) {
        if (tid < off) {
            s1[tid] += s1[tid + off];
            s2[tid] += s2[tid + off];
            s3[tid] += s3[tid + off];
        }
        __syncthreads();
    }
    if (tid == 0)
        lossOut[0] = 0.1f * (0.01f * s3[0] + 0.2f * s2[0] + s1[0]);
}

// ============================================================
extern "C" void kernel_launch(void* const* d_in, const int* in_sizes, int n_in,
                              void* d_out, int out_size)
{
    (void)in_sizes; (void)n_in; (void)out_size;
    const float* feature  = (const float*)d_in[0];
    const float* mask     = (const float*)d_in[1];
    const int*   nmm      = (const int*)  d_in[2];
    const int*   node_idx = (const int*)  d_in[3];
    const float* theta_w  = (const float*)d_in[4];
    const float* theta_b  = (const float*)d_in[5];
    const float* linear   = (const float*)d_in[6];
    const float* rp       = (const float*)d_in[7];
    const float* mhnp     = (const float*)d_in[8];
    const float* mhep     = (const float*)d_in[9];
    const float* pw       = (const float*)d_in[10];
    const float* pb       = (const float*)d_in[11];

    float* out      = (float*)d_out;
    float* predict  = out;
    float* loss     = out + P_ * C_;
    float* node_rep = out + P_ * C_ + 1;

    cudaFuncSetAttribute(k2_mma, cudaFuncAttributeMaxDynamicSharedMemorySize, SMEM_K2);
    cudaFuncSetAttribute(k_gemm_tc<0>, cudaFuncAttributeMaxDynamicSharedMemorySize, SMEM_G);
    cudaFuncSetAttribute(k_gemm_tc<1>, cudaFuncAttributeMaxDynamicSharedMemorySize, SMEM_G);
    cudaFuncSetAttribute(k_gemm_tc<2>, cudaFuncAttributeMaxDynamicSharedMemorySize, SMEM_G);
    cudaFuncSetAttribute(k_gemm_tc<3>, cudaFuncAttributeMaxDynamicSharedMemorySize, SMEM_G);

    k_wconv<<<37 * 65536 / 256, 256>>>(theta_w, rp, mhnp, mhep);
    k_sort<<<1, 256>>>(nmm);
    k_gemm_tc<3><<<N_ / 64, 256, SMEM_G>>>(feature, theta_b);
    k_featT<<<dim3(8, 128), dim3(32, 8)>>>();
    k2_mma<<<NT_ / BM, 512, SMEM_K2>>>(linear, mask);
    k_gemm_tc<0><<<dim3(MAXTILES, T_), 256, SMEM_G>>>(nullptr, nullptr);
    k_gemm_tc<1><<<dim3(MAXTILES, 1), 256, SMEM_G>>>(nullptr, nullptr);
    k_gemm_tc<2><<<dim3(MAXTILES, T_), 256, SMEM_G>>>(nullptr, nullptr);
    k_attn<<<N_, 256>>>(node_rep);
    k_pred<<<P_ / 8, 256>>>(node_rep, node_idx, pw, pb, predict);
    k_reduce<<<1, 256>>>(loss);
}

// round 6
// speedup vs baseline: 4.0739x; 1.0276x over previous
#include <cuda_runtime.h>
#include <cuda_bf16.h>
#include <math.h>
#include <stdint.h>

#define N_ 4096
#define T_ 4
#define F_ 256
#define H_ 8
#define C_ 16
#define P_ 1024
#define D_ 32
#define NT_ (N_*T_)
#define MAXTILES 67

#define BM 128
#define BK 32
#define NCHUNK (N_/BK)
#define APAD 40
#define BPAD 40

// k2_mma dynamic smem offsets (bytes)
#define OFF_A(s,hl)  (((s)*2+(hl)) * (BM*APAD*2))
#define OFF_B(s,hl)  (40960 + ((s)*2+(hl)) * (256*BPAD*2))
#define OFF_RS       122880
#define OFF_RQ       (122880+2048)
#define OFF_RINV     (122880+4096)
#define SMEM_K2      (122880+4096+512+128)

// k_gemm_tc dynamic smem offsets (bytes): M=64 tile
#define GA(s,hl)     (((s)*2+(hl)) * (64*APAD*2))
#define GB(s,hl)     (20480 + ((s)*2+(hl)) * (256*BPAD*2))
#define GIDX         102400
#define GRED         102656
#define SMEM_G       103936
#define GKCH         (F_/BK)

// ---- scratch (static device globals) ----
__device__ float g_feat[N_*F_];
__device__ float g_recon[NT_*F_];
__device__ float g_edgefea[NT_*F_];
__device__ float g_nodeproj[N_*F_];
__device__ float g_edgeproj[NT_*F_];
__device__ float g_rowsum[NT_];
__device__ float g_rowsumsq[NT_];
__device__ float g_rownorm[NT_];
__device__ int   g_perm[N_];
__device__ int   g_tile_s[MAXTILES];
__device__ int   g_tile_start[MAXTILES];
__device__ int   g_tile_cnt[MAXTILES];
__device__ __align__(16) __nv_bfloat16 g_fT_hi[F_*N_];
__device__ __align__(16) __nv_bfloat16 g_fT_lo[F_*N_];
__device__ __align__(16) __nv_bfloat16 g_Whi[37*F_*F_];
__device__ __align__(16) __nv_bfloat16 g_Wlo[37*F_*F_];

// ---- helpers ----
__device__ __forceinline__ uint32_t smem_u32(const void* p) {
    uint32_t a;
    asm("{ .reg .u64 t; cvta.to.shared.u64 t, %1; cvt.u32.u64 %0, t; }"
        : "=r"(a) : "l"(p));
    return a;
}
__device__ __forceinline__ float4 ldg4(const float* p) {
    float4 v;
    asm volatile("ld.global.nc.v4.f32 {%0,%1,%2,%3}, [%4];"
                 : "=f"(v.x), "=f"(v.y), "=f"(v.z), "=f"(v.w) : "l"(p));
    return v;
}
__device__ __forceinline__ void ldm_x4(uint32_t* r, uint32_t addr) {
    asm volatile("ldmatrix.sync.aligned.m8n8.x4.shared.b16 {%0,%1,%2,%3}, [%4];"
                 : "=r"(r[0]), "=r"(r[1]), "=r"(r[2]), "=r"(r[3]) : "r"(addr));
}
__device__ __forceinline__ void mma_bf16(float* d, const uint32_t* a,
                                         uint32_t b0, uint32_t b1) {
    asm volatile("mma.sync.aligned.m16n8k16.row.col.f32.bf16.bf16.f32 "
                 "{%0,%1,%2,%3}, {%4,%5,%6,%7}, {%8,%9}, {%0,%1,%2,%3};"
                 : "+f"(d[0]), "+f"(d[1]), "+f"(d[2]), "+f"(d[3])
                 : "r"(a[0]), "r"(a[1]), "r"(a[2]), "r"(a[3]), "r"(b0), "r"(b1));
}
__device__ __forceinline__ void cpa16(uint32_t dst, const void* src) {
    asm volatile("cp.async.ca.shared.global [%0], [%1], 16;" :: "r"(dst), "l"(src));
}
#define CP_COMMIT() asm volatile("cp.async.commit_group;" ::: "memory")
#define CP_WAIT0()  asm volatile("cp.async.wait_group 0;"  ::: "memory")

// pack 8 ls values (relu(l*m)) from regs -> bf16 hi/lo + row stats
__device__ __forceinline__ void pack_regs(float4 L0, float4 L1, float4 M0, float4 M1,
                                          float& psum, float& psq,
                                          uint32_t* Ah, uint32_t* Al)
{
    float v[8];
    v[0] = fmaxf(L0.x * M0.x, 0.f); v[1] = fmaxf(L0.y * M0.y, 0.f);
    v[2] = fmaxf(L0.z * M0.z, 0.f); v[3] = fmaxf(L0.w * M0.w, 0.f);
    v[4] = fmaxf(L1.x * M1.x, 0.f); v[5] = fmaxf(L1.y * M1.y, 0.f);
    v[6] = fmaxf(L1.z * M1.z, 0.f); v[7] = fmaxf(L1.w * M1.w, 0.f);
    #pragma unroll
    for (int i = 0; i < 8; i++) { psum += v[i]; psq = fmaf(v[i], v[i], psq); }
    #pragma unroll
    for (int p = 0; p < 4; p++) {
        __nv_bfloat162 hp = __floats2bfloat162_rn(v[2*p], v[2*p+1]);
        float r0 = v[2*p]   - __bfloat162float(hp.x);
        float r1 = v[2*p+1] - __bfloat162float(hp.y);
        __nv_bfloat162 lw = __floats2bfloat162_rn(r0, r1);
        Ah[p] = *(uint32_t*)&hp;
        Al[p] = *(uint32_t*)&lw;
    }
}

// plain hi/lo split of 8 fp32 from regs
__device__ __forceinline__ void split_regs(float4 a, float4 b, uint32_t* Ah, uint32_t* Al)
{
    float v[8] = {a.x, a.y, a.z, a.w, b.x, b.y, b.z, b.w};
    #pragma unroll
    for (int q = 0; q < 4; q++) {
        __nv_bfloat162 hp = __floats2bfloat162_rn(v[2*q], v[2*q+1]);
        float r0 = v[2*q]   - __bfloat162float(hp.x);
        float r1 = v[2*q+1] - __bfloat162float(hp.y);
        __nv_bfloat162 lw = __floats2bfloat162_rn(r0, r1);
        Ah[q] = *(uint32_t*)&hp;
        Al[q] = *(uint32_t*)&lw;
    }
}

// ============================================================
// K2-MMA: recon = ls @ feat, fused; software-pipelined so the
// LDGs for chunk c+1 issue BEFORE the MMA of chunk c and are
// consumed (packed) AFTER it.
// ============================================================
__global__ __launch_bounds__(512, 1) void k2_mma(const float* __restrict__ linear,
                                                 const float* __restrict__ mask)
{
    extern __shared__ char sm[];
    const uint32_t sb = smem_u32(sm);
    const int tid = threadIdx.x;
    const int wid = tid >> 5, lane = tid & 31;
    const int warp_m = wid & 3, warp_n = wid >> 2;
    const int ntBase = blockIdx.x * BM;

    const int arow = tid >> 2;
    const int akof = (tid & 3) * 8;
    const float* lptr = linear + (size_t)(ntBase + arow) * N_ + akof;
    const float* mptr = mask   + (size_t)(ntBase + arow) * N_ + akof;
    const uint32_t aSt = (uint32_t)(arow * APAD + akof) * 2;

    const int bhl = tid >> 8;
    const int bn  = tid & 255;
    const char* bsrc = (const char*)((bhl ? g_fT_lo : g_fT_hi) + (size_t)bn * N_);
    const uint32_t bSt = (uint32_t)(bn * BPAD) * 2;

    float psum = 0.f, psq = 0.f;
    uint32_t Ah[4], Al[4];
    float4 La, Lb, Ma, Mb;

    const int aRowL = warp_m * 32 + (lane & 7) + ((lane >> 3) & 1) * 8;
    const int aColL = (lane >> 4) * 8;
    const int bRowL = warp_n * 64 + (lane & 7) + ((lane >> 4) & 1) * 8;
    const int bColL = ((lane >> 3) & 1) * 8;

    // prologue: chunk 0
    La = ldg4(lptr); Lb = ldg4(lptr + 4);
    Ma = ldg4(mptr); Mb = ldg4(mptr + 4);
    {
        uint32_t d = sb + OFF_B(0, bhl) + bSt;
        #pragma unroll
        for (int q = 0; q < 4; q++) cpa16(d + q * 16, bsrc + q * 16);
    }
    CP_COMMIT();
    pack_regs(La, Lb, Ma, Mb, psum, psq, Ah, Al);
    *(uint4*)(sm + OFF_A(0,0) + aSt) = make_uint4(Ah[0], Ah[1], Ah[2], Ah[3]);
    *(uint4*)(sm + OFF_A(0,1) + aSt) = make_uint4(Al[0], Al[1], Al[2], Al[3]);
    CP_WAIT0();
    __syncthreads();

    float acc[2][8][4];
    #pragma unroll
    for (int i = 0; i < 2; i++)
        #pragma unroll
        for (int j = 0; j < 8; j++)
            #pragma unroll
            for (int q = 0; q < 4; q++) acc[i][j][q] = 0.f;

    for (int c = 0; c < NCHUNK; c++) {
        const int s = c & 1;
        const bool more = (c + 1 < NCHUNK);
        if (more) {
            // issue next-chunk loads BEFORE the MMA block (latency hidden)
            uint32_t d = sb + OFF_B(s ^ 1, bhl) + bSt;
            const char* src = bsrc + (size_t)(c + 1) * BK * 2;
            #pragma unroll
            for (int q = 0; q < 4; q++) cpa16(d + q * 16, src + q * 16);
            CP_COMMIT();
            const float* lp = lptr + (c + 1) * BK;
            const float* mp = mptr + (c + 1) * BK;
            La = ldg4(lp); Lb = ldg4(lp + 4);
            Ma = ldg4(mp); Mb = ldg4(mp + 4);
        }

        const uint32_t aHi = sb + OFF_A(s,0), aLo = sb + OFF_A(s,1);
        const uint32_t bHi = sb + OFF_B(s,0), bLo = sb + OFF_B(s,1);

        #pragma unroll
        for (int ks = 0; ks < BK; ks += 16) {
            uint32_t ah[2][4], alr[2][4], bb[4][4];
            ldm_x4(ah[0], aHi + (uint32_t)((aRowL)      * APAD + ks + aColL) * 2);
            ldm_x4(ah[1], aHi + (uint32_t)((aRowL + 16) * APAD + ks + aColL) * 2);
            #pragma unroll
            for (int g = 0; g < 4; g++)
                ldm_x4(bb[g], bHi + (uint32_t)((bRowL + g * 16) * BPAD + ks + bColL) * 2);
            #pragma unroll
            for (int mf = 0; mf < 2; mf++)
                #pragma unroll
                for (int nf = 0; nf < 8; nf++)
                    mma_bf16(acc[mf][nf], ah[mf],
                             bb[nf >> 1][(nf & 1) * 2], bb[nf >> 1][(nf & 1) * 2 + 1]);
            ldm_x4(alr[0], aLo + (uint32_t)((aRowL)      * APAD + ks + aColL) * 2);
            ldm_x4(alr[1], aLo + (uint32_t)((aRowL + 16) * APAD + ks + aColL) * 2);
            #pragma unroll
            for (int mf = 0; mf < 2; mf++)
                #pragma unroll
                for (int nf = 0; nf < 8; nf++)
                    mma_bf16(acc[mf][nf], alr[mf],
                             bb[nf >> 1][(nf & 1) * 2], bb[nf >> 1][(nf & 1) * 2 + 1]);
            #pragma unroll
            for (int g = 0; g < 4; g++)
                ldm_x4(bb[g], bLo + (uint32_t)((bRowL + g * 16) * BPAD + ks + bColL) * 2);
            #pragma unroll
            for (int mf = 0; mf < 2; mf++)
                #pragma unroll
                for (int nf = 0; nf < 8; nf++)
                    mma_bf16(acc[mf][nf], ah[mf],
                             bb[nf >> 1][(nf & 1) * 2], bb[nf >> 1][(nf & 1) * 2 + 1]);
        }

        if (more) {
            pack_regs(La, Lb, Ma, Mb, psum, psq, Ah, Al);
            *(uint4*)(sm + OFF_A(s^1,0) + aSt) = make_uint4(Ah[0], Ah[1], Ah[2], Ah[3]);
            *(uint4*)(sm + OFF_A(s^1,1) + aSt) = make_uint4(Al[0], Al[1], Al[2], Al[3]);
            CP_WAIT0();
            __syncthreads();
        }
    }

    ((float*)(sm + OFF_RS))[arow * 4 + (tid & 3)] = psum;
    ((float*)(sm + OFF_RQ))[arow * 4 + (tid & 3)] = psq;
    __syncthreads();
    if (tid < BM) {
        const float* rs = (const float*)(sm + OFF_RS) + tid * 4;
        const float* rq = (const float*)(sm + OFF_RQ) + tid * 4;
        float ss = (rs[0] + rs[1]) + (rs[2] + rs[3]);
        float sq = (rq[0] + rq[1]) + (rq[2] + rq[3]);
        g_rowsum[ntBase + tid]   = ss;
        g_rowsumsq[ntBase + tid] = sq;
        ((float*)(sm + OFF_RINV))[tid] = 1.f / (ss + 1.f);
    }
    __syncthreads();
    const float* rinv = (const float*)(sm + OFF_RINV);

    #pragma unroll
    for (int mf = 0; mf < 2; mf++) {
        #pragma unroll
        for (int half = 0; half < 2; half++) {
            int row = warp_m * 32 + mf * 16 + half * 8 + (lane >> 2);
            int nt = ntBase + row;
            float inv = rinv[row];
            const float* fb = g_feat + (size_t)(nt >> 2) * F_;
            float* rb = g_recon   + (size_t)nt * F_;
            float* eb = g_edgefea + (size_t)nt * F_;
            #pragma unroll
            for (int nf = 0; nf < 8; nf++) {
                int col = warp_n * 64 + nf * 8 + (lane & 3) * 2;
                float d0 = acc[mf][nf][half * 2];
                float d1 = acc[mf][nf][half * 2 + 1];
                *(float2*)(rb + col) = make_float2(d0, d1);
                float2 fv = *(const float2*)(fb + col);
                *(float2*)(eb + col) = make_float2((d0 + fv.x) * inv, (d1 + fv.y) * inv);
            }
        }
    }
}

// ============================================================
// K_gemm_tc<MODE>: tensor-core GEMM, M-tile 64, N=256, K=256.
//  MODE 0: inp_proj diff -> rownorm   MODE 1: node_projd
//  MODE 2: edge_projd                 MODE 3: feature@theta^T+b
// ============================================================
template<int MODE>
__global__ __launch_bounds__(256, 2) void k_gemm_tc(const float* __restrict__ Ain,
                                                    const float* __restrict__ bias)
{
    extern __shared__ char sm[];
    const uint32_t sb = smem_u32(sm);
    const int tid = threadIdx.x;
    const int wid = tid >> 5, lane = tid & 31;
    const int warp_m = wid & 1, warp_n = wid >> 1;

    int s = 0, j = 0, cnt = 64, mBase = 0;
    int* sidx = (int*)(sm + GIDX);
    if (MODE == 3) {
        mBase = blockIdx.x * 64;
    } else {
        const int t = blockIdx.x;
        cnt = g_tile_cnt[t];
        if (cnt == 0) return;
        s = g_tile_s[t];
        j = blockIdx.y;
        const int start = g_tile_start[t];
        if (tid < 64) sidx[tid] = g_perm[start + min(tid, cnt - 1)];
        __syncthreads();
    }

    const int arow = tid >> 2;
    const int akof = (tid & 3) * 8;
    const float* aptr;
    if (MODE == 3)      aptr = Ain + (size_t)(mBase + arow) * F_ + akof;
    else if (MODE == 2) aptr = g_edgefea + ((size_t)sidx[arow] * T_ + j) * F_ + akof;
    else                aptr = g_feat + (size_t)sidx[arow] * F_ + akof;
    const uint32_t aSt = (uint32_t)(arow * APAD + akof) * 2;

    int z;
    if (MODE == 3)      z = 0;
    else if (MODE == 0) z = 1 + s * T_ + j;
    else if (MODE == 1) z = 17 + s;
    else                z = 21 + s * T_ + j;
    const char* bh_src = (const char*)(g_Whi + (size_t)z * F_ * F_ + (size_t)tid * F_);
    const char* bl_src = (const char*)(g_Wlo + (size_t)z * F_ * F_ + (size_t)tid * F_);
    const uint32_t bSt = (uint32_t)(tid * BPAD) * 2;

    const int aRowL = warp_m * 32 + (lane & 7) + ((lane >> 3) & 1) * 8;
    const int aColL = (lane >> 4) * 8;
    const int bRowL = warp_n * 64 + (lane & 7) + ((lane >> 4) & 1) * 8;
    const int bColL = ((lane >> 3) & 1) * 8;

    uint32_t Ah[4], Al[4];
    float4 Aa, Ab;

    Aa = ldg4(aptr); Ab = ldg4(aptr + 4);
    {
        uint32_t dh = sb + GB(0,0) + bSt;
        uint32_t dl = sb + GB(0,1) + bSt;
        #pragma unroll
        for (int q = 0; q < 4; q++) {
            cpa16(dh + q * 16, bh_src + q * 16);
            cpa16(dl + q * 16, bl_src + q * 16);
        }
    }
    CP_COMMIT();
    split_regs(Aa, Ab, Ah, Al);
    *(uint4*)(sm + GA(0,0) + aSt) = make_uint4(Ah[0], Ah[1], Ah[2], Ah[3]);
    *(uint4*)(sm + GA(0,1) + aSt) = make_uint4(Al[0], Al[1], Al[2], Al[3]);
    CP_WAIT0();
    __syncthreads();

    float acc[2][8][4];
    #pragma unroll
    for (int i = 0; i < 2; i++)
        #pragma unroll
        for (int q = 0; q < 8; q++)
            #pragma unroll
            for (int e = 0; e < 4; e++) acc[i][q][e] = 0.f;

    for (int c = 0; c < GKCH; c++) {
        const int st = c & 1;
        const bool more = (c + 1 < GKCH);
        if (more) {
            uint32_t dh = sb + GB(st ^ 1, 0) + bSt;
            uint32_t dl = sb + GB(st ^ 1, 1) + bSt;
            const char* sh = bh_src + (size_t)(c + 1) * BK * 2;
            const char* sl = bl_src + (size_t)(c + 1) * BK * 2;
            #pragma unroll
            for (int q = 0; q < 4; q++) {
                cpa16(dh + q * 16, sh + q * 16);
                cpa16(dl + q * 16, sl + q * 16);
            }
            CP_COMMIT();
            Aa = ldg4(aptr + (c + 1) * BK);
            Ab = ldg4(aptr + (c + 1) * BK + 4);
        }

        const uint32_t aHi = sb + GA(st,0), aLo = sb + GA(st,1);
        const uint32_t bHi = sb + GB(st,0), bLo = sb + GB(st,1);

        #pragma unroll
        for (int ks = 0; ks < BK; ks += 16) {
            uint32_t ah[2][4], alr[2][4], bb[4][4];
            ldm_x4(ah[0], aHi + (uint32_t)((aRowL)      * APAD + ks + aColL) * 2);
            ldm_x4(ah[1], aHi + (uint32_t)((aRowL + 16) * APAD + ks + aColL) * 2);
            #pragma unroll
            for (int g = 0; g < 4; g++)
                ldm_x4(bb[g], bHi + (uint32_t)((bRowL + g * 16) * BPAD + ks + bColL) * 2);
            #pragma unroll
            for (int mf = 0; mf < 2; mf++)
                #pragma unroll
                for (int nf = 0; nf < 8; nf++)
                    mma_bf16(acc[mf][nf], ah[mf],
                             bb[nf >> 1][(nf & 1) * 2], bb[nf >> 1][(nf & 1) * 2 + 1]);
            ldm_x4(alr[0], aLo + (uint32_t)((aRowL)      * APAD + ks + aColL) * 2);
            ldm_x4(alr[1], aLo + (uint32_t)((aRowL + 16) * APAD + ks + aColL) * 2);
            #pragma unroll
            for (int mf = 0; mf < 2; mf++)
                #pragma unroll
                for (int nf = 0; nf < 8; nf++)
                    mma_bf16(acc[mf][nf], alr[mf],
                             bb[nf >> 1][(nf & 1) * 2], bb[nf >> 1][(nf & 1) * 2 + 1]);
            #pragma unroll
            for (int g = 0; g < 4; g++)
                ldm_x4(bb[g], bLo + (uint32_t)((bRowL + g * 16) * BPAD + ks + bColL) * 2);
            #pragma unroll
            for (int mf = 0; mf < 2; mf++)
                #pragma unroll
                for (int nf = 0; nf < 8; nf++)
                    mma_bf16(acc[mf][nf], ah[mf],
                             bb[nf >> 1][(nf & 1) * 2], bb[nf >> 1][(nf & 1) * 2 + 1]);
        }

        if (more) {
            split_regs(Aa, Ab, Ah, Al);
            *(uint4*)(sm + GA(st^1,0) + aSt) = make_uint4(Ah[0], Ah[1], Ah[2], Ah[3]);
            *(uint4*)(sm + GA(st^1,1) + aSt) = make_uint4(Al[0], Al[1], Al[2], Al[3]);
            CP_WAIT0();
            __syncthreads();
        }
    }

    if (MODE == 0) {
        float* sred = (float*)(sm + GRED);
        #pragma unroll
        for (int mf = 0; mf < 2; mf++) {
            #pragma unroll
            for (int half = 0; half < 2; half++) {
                int row = warp_m * 32 + mf * 16 + half * 8 + (lane >> 2);
                int node = sidx[row];
                const float* rr = g_recon + ((size_t)node * T_ + j) * F_;
                float part = 0.f;
                #pragma unroll
                for (int nf = 0; nf < 8; nf++) {
                    int col = warp_n * 64 + nf * 8 + (lane & 3) * 2;
                    float2 rv = *(const float2*)(rr + col);
                    float d0 = acc[mf][nf][half * 2]     - rv.x;
                    float d1 = acc[mf][nf][half * 2 + 1] - rv.y;
                    part = fmaf(d0, d0, part);
                    part = fmaf(d1, d1, part);
                }
                part += __shfl_xor_sync(0xffffffffu, part, 1);
                part += __shfl_xor_sync(0xffffffffu, part, 2);
                if ((lane & 3) == 0) sred[row * 4 + warp_n] = part;
            }
        }
        __syncthreads();
        if (tid < 64) {
            const float* r4 = sred + tid * 4;
            float tot = (r4[0] + r4[1]) + (r4[2] + r4[3]);
            if (tid < cnt)
                g_rownorm[sidx[tid] * T_ + j] = sqrtf(tot);
        }
    } else {
        #pragma unroll
        for (int mf = 0; mf < 2; mf++) {
            #pragma unroll
            for (int half = 0; half < 2; half++) {
                int row = warp_m * 32 + mf * 16 + half * 8 + (lane >> 2);
                float* ob;
                if (MODE == 3) {
                    ob = g_feat + (size_t)(mBase + row) * F_;
                } else {
                    if (row >= cnt) continue;
                    int node = sidx[row];
                    if (MODE == 1) ob = g_nodeproj + (size_t)node * F_;
                    else           ob = g_edgeproj + ((size_t)node * T_ + j) * F_;
                }
                #pragma unroll
                for (int nf = 0; nf < 8; nf++) {
                    int col = warp_n * 64 + nf * 8 + (lane & 3) * 2;
                    float d0 = acc[mf][nf][half * 2];
                    float d1 = acc[mf][nf][half * 2 + 1];
                    if (MODE == 3) {
                        d0 += bias[col];
                        d1 += bias[col + 1];
                    }
                    *(float2*)(ob + col) = make_float2(d0, d1);
                }
            }
        }
    }
}

// ============================================================
// K_wconv: weights fp32 -> bf16 hi/lo, vectorized x4
// ============================================================
__global__ __launch_bounds__(256) void k_wconv(const float* __restrict__ th,
                                               const float* __restrict__ rp,
                                               const float* __restrict__ np,
                                               const float* __restrict__ ep)
{
    int i4 = blockIdx.x * 256 + threadIdx.x;
    int i = i4 * 4;
    int z = i >> 16;
    int off = i & 65535;
    const float* src;
    if (z == 0)      src = th;
    else if (z < 17) src = rp + (size_t)(z - 1)  * 65536;
    else if (z < 21) src = np + (size_t)(z - 17) * 65536;
    else             src = ep + (size_t)(z - 21) * 65536;
    float4 v = ldg4(src + off);
    __nv_bfloat162 h0 = __floats2bfloat162_rn(v.x, v.y);
    __nv_bfloat162 h1 = __floats2bfloat162_rn(v.z, v.w);
    float l0 = v.x - __bfloat162float(h0.x);
    float l1 = v.y - __bfloat162float(h0.y);
    float l2 = v.z - __bfloat162float(h1.x);
    float l3 = v.w - __bfloat162float(h1.y);
    __nv_bfloat162 w0 = __floats2bfloat162_rn(l0, l1);
    __nv_bfloat162 w1 = __floats2bfloat162_rn(l2, l3);
    *(uint2*)(g_Whi + i) = make_uint2(*(uint32_t*)&h0, *(uint32_t*)&h1);
    *(uint2*)(g_Wlo + i) = make_uint2(*(uint32_t*)&w0, *(uint32_t*)&w1);
}

// ============================================================
// K_featT: featT hi/lo bf16 [F_][N_] from g_feat
// ============================================================
__global__ void k_featT()
{
    __shared__ float tile[32][33];
    int x = blockIdx.x * 32 + threadIdx.x;
    int y = blockIdx.y * 32 + threadIdx.y;
    #pragma unroll
    for (int i = 0; i < 32; i += 8)
        tile[threadIdx.y + i][threadIdx.x] = g_feat[(size_t)(y + i) * F_ + x];
    __syncthreads();
    int f2 = blockIdx.x * 32 + threadIdx.y;
    int n2 = blockIdx.y * 32 + threadIdx.x;
    #pragma unroll
    for (int i = 0; i < 32; i += 8) {
        float v = tile[threadIdx.x][threadIdx.y + i];
        __nv_bfloat16 hi = __float2bfloat16(v);
        __nv_bfloat16 lo = __float2bfloat16(v - __bfloat162float(hi));
        g_fT_hi[(size_t)(f2 + i) * N_ + n2] = hi;
        g_fT_lo[(size_t)(f2 + i) * N_ + n2] = lo;
    }
}

// ============================================================
// K_sort
// ============================================================
__global__ __launch_bounds__(256) void k_sort(const int* __restrict__ nmm)
{
    __shared__ int hist[4][256];
    __shared__ int basep[4][256];
    __shared__ int btot[4];
    __shared__ int boff[4];

    const int tid = threadIdx.x;
    const int r0 = tid * 16;
    int myb[16];
    int c[4] = {0, 0, 0, 0};
    #pragma unroll
    for (int i = 0; i < 16; i++) {
        int b = nmm[r0 + i];
        myb[i] = b;
        c[b]++;
    }
    #pragma unroll
    for (int b = 0; b < 4; b++) hist[b][tid] = c[b];
    __syncthreads();

    const int w = tid >> 5, lane = tid & 31;
    if (w < 4) {
        int b = w;
        int loc[8];
        int sum = 0;
        #pragma unroll
        for (int q = 0; q < 8; q++) {
            loc[q] = sum;
            sum += hist[b][lane * 8 + q];
        }
        int pre = sum;
        #pragma unroll
        for (int off = 1; off < 32; off <<= 1) {
            int v = __shfl_up_sync(0xffffffffu, pre, off);
            if (lane >= off) pre += v;
        }
        int tot = __shfl_sync(0xffffffffu, pre, 31);
        pre -= sum;
        #pragma unroll
        for (int q = 0; q < 8; q++) basep[b][lane * 8 + q] = pre + loc[q];
        if (lane == 31) btot[b] = tot;
    }
    __syncthreads();

    if (tid == 0) {
        int off = 0, t = 0;
        for (int b = 0; b < 4; b++) {
            boff[b] = off;
            int cnt = btot[b];
            for (int k = 0; k < cnt; k += 64) {
                g_tile_s[t] = b;
                g_tile_start[t] = off + k;
                g_tile_cnt[t] = min(64, cnt - k);
                t++;
            }
            off += cnt;
        }
        for (; t < MAXTILES; t++) { g_tile_cnt[t] = 0; g_tile_s[t] = 0; g_tile_start[t] = 0; }
    }
    __syncthreads();

    int pos[4];
    #pragma unroll
    for (int b = 0; b < 4; b++) pos[b] = boff[b] + basep[b][tid];
    #pragma unroll
    for (int i = 0; i < 16; i++) {
        int b = myb[i];
        g_perm[pos[b]++] = r0 + i;
    }
}

// ============================================================
// K_attn
// ============================================================
__global__ __launch_bounds__(256) void k_attn(float* __restrict__ node_rep)
{
    const int i = blockIdx.x, tid = threadIdx.x;
    const int h = tid >> 5, lane = tid & 31;
    __shared__ float sw[T_][H_];

    float np = g_nodeproj[(size_t)i * F_ + tid];
    const float inv = rsqrtf((float)D_);

    #pragma unroll
    for (int t = 0; t < T_; t++) {
        float v = np * g_edgeproj[((size_t)i * T_ + t) * F_ + tid];
        #pragma unroll
        for (int off = 16; off > 0; off >>= 1)
            v += __shfl_down_sync(0xffffffffu, v, off);
        if (lane == 0) sw[t][h] = v * inv;
    }
    __syncthreads();

    if (tid < T_) {
        int t = tid;
        float mx = sw[t][0];
        #pragma unroll
        for (int hh = 1; hh < H_; hh++) mx = fmaxf(mx, sw[t][hh]);
        float sm = 0.f;
        #pragma unroll
        for (int hh = 0; hh < H_; hh++) {
            float e = expf(sw[t][hh] - mx);
            sw[t][hh] = e;
            sm += e;
        }
        float r = 1.f / sm;
        #pragma unroll
        for (int hh = 0; hh < H_; hh++) sw[t][hh] *= r;
    }
    __syncthreads();

    float rep = 0.f;
    #pragma unroll
    for (int t = 0; t < T_; t++)
        rep += fmaxf(sw[t][h] * g_edgefea[((size_t)i * T_ + t) * F_ + tid], 0.f);
    node_rep[(size_t)i * F_ + tid] = rep;
}

// ============================================================
// K_pred
// ============================================================
__global__ __launch_bounds__(256) void k_pred(const float* __restrict__ node_rep,
                                              const int* __restrict__ node_idx,
                                              const float* __restrict__ pw,
                                              const float* __restrict__ pb,
                                              float* __restrict__ predict)
{
    const int warp = threadIdx.x >> 5, lane = threadIdx.x & 31;
    const int p = blockIdx.x * 8 + warp;
    const float* a = node_rep + (size_t)node_idx[p] * F_;

    float part[C_];
    #pragma unroll
    for (int c = 0; c < C_; c++) part[c] = 0.f;
    for (int f = lane; f < F_; f += 32) {
        float av = a[f];
        #pragma unroll
        for (int c = 0; c < C_; c++)
            part[c] = fmaf(av, pw[c * F_ + f], part[c]);
    }
    #pragma unroll
    for (int c = 0; c < C_; c++)
        #pragma unroll
        for (int off = 16; off > 0; off >>= 1)
            part[c] += __shfl_down_sync(0xffffffffu, part[c], off);

    if (lane == 0) {
        float sig[C_];
        float mx = -1e30f;
        #pragma unroll
        for (int c = 0; c < C_; c++) {
            float l = part[c] + pb[c];
            float sg = 1.f / (1.f + expf(-l));
            sig[c] = sg;
            mx = fmaxf(mx, sg);
        }
        float sm = 0.f;
        #pragma unroll
        for (int c = 0; c < C_; c++) {
            float e = expf(sig[c] - mx);
            sig[c] = e;
            sm += e;
        }
        float r = 1.f / sm;
        #pragma unroll
        for (int c = 0; c < C_; c++)
            predict[(size_t)p * C_ + c] = sig[c] * r;
    }
}

// ============================================================
// K_reduce
// ============================================================
__global__ __launch_bounds__(256) void k_reduce(float* __restrict__ lossOut)
{
    __shared__ float s1[256], s2[256], s3[256];
    int tid = threadIdx.x;
    float l1 = 0.f, l2 = 0.f, re = 0.f;
    for (int i = tid; i < NT_; i += 256) {
        l1 += g_rowsum[i];
        l2 += sqrtf(g_rowsumsq[i]);
        re += g_rownorm[i];
    }
    s1[tid] = l1; s2[tid] = l2; s3[tid] = re;
    __syncthreads();
    for (int off = 128; off > 0; off >>= 1) {
        if (tid < off) {
            s1[tid] += s1[tid + off];
            s2[tid] += s2[tid + off];
            s3[tid] += s3[tid + off];
        }
        __syncthreads();
    }
    if (tid == 0)
        lossOut[0] = 0.1f * (0.01f * s3[0] + 0.2f * s2[0] + s1[0]);
}

// ============================================================
extern "C" void kernel_launch(void* const* d_in, const int* in_sizes, int n_in,
                              void* d_out, int out_size)
{
    (void)in_sizes; (void)n_in; (void)out_size;
    const float* feature  = (const float*)d_in[0];
    const float* mask     = (const float*)d_in[1];
    const int*   nmm      = (const int*)  d_in[2];
    const int*   node_idx = (const int*)  d_in[3];
    const float* theta_w  = (const float*)d_in[4];
    const float* theta_b  = (const float*)d_in[5];
    const float* linear   = (const float*)d_in[6];
    const float* rp       = (const float*)d_in[7];
    const float* mhnp     = (const float*)d_in[8];
    const float* mhep     = (const float*)d_in[9];
    const float* pw       = (const float*)d_in[10];
    const float* pb       = (const float*)d_in[11];

    float* out      = (float*)d_out;
    float* predict  = out;
    float* loss     = out + P_ * C_;
    float* node_rep = out + P_ * C_ + 1;

    cudaFuncSetAttribute(k2_mma, cudaFuncAttributeMaxDynamicSharedMemorySize, SMEM_K2);
    cudaFuncSetAttribute(k_gemm_tc<0>, cudaFuncAttributeMaxDynamicSharedMemorySize, SMEM_G);
    cudaFuncSetAttribute(k_gemm_tc<1>, cudaFuncAttributeMaxDynamicSharedMemorySize, SMEM_G);
    cudaFuncSetAttribute(k_gemm_tc<2>, cudaFuncAttributeMaxDynamicSharedMemorySize, SMEM_G);
    cudaFuncSetAttribute(k_gemm_tc<3>, cudaFuncAttributeMaxDynamicSharedMemorySize, SMEM_G);

    k_wconv<<<37 * 65536 / 1024, 256>>>(theta_w, rp, mhnp, mhep);
    k_sort<<<1, 256>>>(nmm);
    k_gemm_tc<3><<<N_ / 64, 256, SMEM_G>>>(feature, theta_b);
    k_featT<<<dim3(8, 128), dim3(32, 8)>>>();
    k2_mma<<<NT_ / BM, 512, SMEM_K2>>>(linear, mask);
    k_gemm_tc<0><<<dim3(MAXTILES, T_), 256, SMEM_G>>>(nullptr, nullptr);
    k_gemm_tc<1><<<dim3(MAXTILES, 1), 256, SMEM_G>>>(nullptr, nullptr);
    k_gemm_tc<2><<<dim3(MAXTILES, T_), 256, SMEM_G>>>(nullptr, nullptr);
    k_attn<<<N_, 256>>>(node_rep);
    k_pred<<<P_ / 8, 256>>>(node_rep, node_idx, pw, pb, predict);
    k_reduce<<<1, 256>>>(loss);
}